// round 1
// baseline (speedup 1.0000x reference)
#include <cuda_runtime.h>
#include <cstddef>

#define BB 4
#define TT 4096
#define DD 1024
#define NN 64
#define RR 16
#define KK 4

// Scratch (device globals — no allocation allowed)
__device__ float g_proj[BB * TT * NN];
__device__ float g_delta[BB * TT * NN];
__device__ float g_states[BB * TT * NN];

// ---------------------------------------------------------------------------
// Stage 1: projected = (x + causal_depthwise_conv(x)) @ in_w^T + in_b   [BT,64]
//          delta     = tanh(x @ dt_w^T + dt_b) @ tr_w^T                 [BT,64]
// One block = 64 rows (never straddles a batch: 4096 % 64 == 0).
// Tiled GEMM over K=1024 in chunks of 32. conv fused into A-tile build.
// ---------------------------------------------------------------------------
__global__ __launch_bounds__(256) void stage1_kernel(
    const float* __restrict__ x,
    const float* __restrict__ conv_w,
    const float* __restrict__ in_w,
    const float* __restrict__ in_b,
    const float* __restrict__ dt_w,
    const float* __restrict__ dt_b,
    const float* __restrict__ tr_w)
{
    // xs: plain x tile, [k][row]; rows 0..63 = tile rows, 64..66 = halo rows t0-3..t0-1
    __shared__ float xs[32 * 72];
    __shared__ float as[32 * 72];   // x + conv tile, rows 0..63
    __shared__ float wb[32 * 80];   // [k][c]: c<64 -> in_w, c>=64 -> dt_w
    __shared__ float scw[32 * 4];   // conv_w chunk
    __shared__ float sdm[64 * 16];  // tanh(mid) per row
    __shared__ float str[16 * 64];  // tr_w transposed: str[r*64+n] = tr_w[n][r]

    const int tid = threadIdx.x;
    const int base = blockIdx.x * 64;        // global row (b*T + t)
    const int t0 = base & (TT - 1);          // t within batch
    const int cg = tid & 15;                 // column group (0..15)
    const int rg = tid >> 4;                 // row group (0..15)

    // load tr_w transposed once
    for (int idx = tid; idx < NN * RR; idx += 256) {
        int n = idx >> 4, r = idx & 15;
        str[r * 64 + n] = tr_w[idx];
    }

    float acc[4][5];
#pragma unroll
    for (int i = 0; i < 4; i++)
#pragma unroll
        for (int m = 0; m < 5; m++) acc[i][m] = 0.f;

    for (int k0 = 0; k0 < DD; k0 += 32) {
        // ---- load x tile (67 rows x 32 cols), transposed into xs[k][row] ----
        for (int idx = tid; idx < 67 * 8; idx += 256) {
            int ri = idx >> 3, kq = idx & 7;
            int t = (ri < 64) ? (t0 + ri) : (t0 + ri - 67);  // 64..66 -> t0-3..t0-1
            float4 v = make_float4(0.f, 0.f, 0.f, 0.f);
            if (t >= 0) {
                v = *(const float4*)(x + (size_t)(base - t0 + t) * DD + k0 + 4 * kq);
            }
            int kk = 4 * kq;
            xs[(kk + 0) * 72 + ri] = v.x;
            xs[(kk + 1) * 72 + ri] = v.y;
            xs[(kk + 2) * 72 + ri] = v.z;
            xs[(kk + 3) * 72 + ri] = v.w;
        }
        // ---- load weights: wb[k][c] ----
        for (int idx = tid; idx < 80 * 32; idx += 256) {
            int c = idx >> 5, kk = idx & 31;
            float w = (c < 64) ? in_w[(size_t)c * DD + k0 + kk]
                               : dt_w[(size_t)(c - 64) * DD + k0 + kk];
            wb[kk * 80 + c] = w;
        }
        // ---- load conv_w chunk ----
        if (tid < 128) {
            int kk = tid >> 2, j = tid & 3;
            scw[kk * 4 + j] = conv_w[(size_t)(k0 + kk) * KK + j];
        }
        __syncthreads();

        // ---- build conv A-tile: as[k][r] = x[r] + sum_j cw[j]*x[r-3+j] ----
        for (int idx = tid; idx < 32 * 64; idx += 256) {
            int kk = idx >> 6, r = idx & 63;
            const float* xr = xs + kk * 72;
            float c0 = scw[kk * 4 + 0], c1 = scw[kk * 4 + 1];
            float c2 = scw[kk * 4 + 2], c3 = scw[kk * 4 + 3];
            int rm1 = r - 1; if (rm1 < 0) rm1 += 67;
            int rm2 = r - 2; if (rm2 < 0) rm2 += 67;
            int rm3 = r - 3; if (rm3 < 0) rm3 += 67;
            float v = xr[r];
            v = fmaf(c3, xr[r], v);
            v = fmaf(c2, xr[rm1], v);
            v = fmaf(c1, xr[rm2], v);
            v = fmaf(c0, xr[rm3], v);
            as[kk * 72 + r] = v;
        }
        __syncthreads();

        // ---- FFMA main loop ----
#pragma unroll 8
        for (int kk = 0; kk < 32; kk++) {
            float4 av = *(float4*)(as + kk * 72 + 4 * rg);
            float4 xv = *(float4*)(xs + kk * 72 + 4 * rg);
            float b0 = wb[kk * 80 + cg];
            float b1 = wb[kk * 80 + cg + 16];
            float b2 = wb[kk * 80 + cg + 32];
            float b3 = wb[kk * 80 + cg + 48];
            float b4 = wb[kk * 80 + cg + 64];
            float a0 = av.x, a1 = av.y, a2 = av.z, a3 = av.w;
            float x0 = xv.x, x1 = xv.y, x2 = xv.z, x3 = xv.w;
            acc[0][0] = fmaf(a0, b0, acc[0][0]);
            acc[1][0] = fmaf(a1, b0, acc[1][0]);
            acc[2][0] = fmaf(a2, b0, acc[2][0]);
            acc[3][0] = fmaf(a3, b0, acc[3][0]);
            acc[0][1] = fmaf(a0, b1, acc[0][1]);
            acc[1][1] = fmaf(a1, b1, acc[1][1]);
            acc[2][1] = fmaf(a2, b1, acc[2][1]);
            acc[3][1] = fmaf(a3, b1, acc[3][1]);
            acc[0][2] = fmaf(a0, b2, acc[0][2]);
            acc[1][2] = fmaf(a1, b2, acc[1][2]);
            acc[2][2] = fmaf(a2, b2, acc[2][2]);
            acc[3][2] = fmaf(a3, b2, acc[3][2]);
            acc[0][3] = fmaf(a0, b3, acc[0][3]);
            acc[1][3] = fmaf(a1, b3, acc[1][3]);
            acc[2][3] = fmaf(a2, b3, acc[2][3]);
            acc[3][3] = fmaf(a3, b3, acc[3][3]);
            acc[0][4] = fmaf(x0, b4, acc[0][4]);
            acc[1][4] = fmaf(x1, b4, acc[1][4]);
            acc[2][4] = fmaf(x2, b4, acc[2][4]);
            acc[3][4] = fmaf(x3, b4, acc[3][4]);
        }
        __syncthreads();
    }

    // ---- epilogue: projected + bias; tanh of delta-mid into smem ----
    float dtb = dt_b[cg];
#pragma unroll
    for (int i = 0; i < 4; i++) {
        int grow = base + 4 * rg + i;
#pragma unroll
        for (int m = 0; m < 4; m++) {
            int c = cg + 16 * m;
            g_proj[(size_t)grow * NN + c] = acc[i][m] + in_b[c];
        }
        sdm[(4 * rg + i) * 16 + cg] = tanhf(acc[i][4] + dtb);
    }
    __syncthreads();

    // ---- delta = sdm @ tr_w^T (tiny K=16 GEMM) ----
    float a2[4][4];
#pragma unroll
    for (int i = 0; i < 4; i++)
#pragma unroll
        for (int j = 0; j < 4; j++) a2[i][j] = 0.f;
#pragma unroll
    for (int r = 0; r < 16; r++) {
        float d0 = sdm[(4 * rg + 0) * 16 + r];
        float d1 = sdm[(4 * rg + 1) * 16 + r];
        float d2 = sdm[(4 * rg + 2) * 16 + r];
        float d3 = sdm[(4 * rg + 3) * 16 + r];
        float w0 = str[r * 64 + 4 * cg + 0];
        float w1 = str[r * 64 + 4 * cg + 1];
        float w2 = str[r * 64 + 4 * cg + 2];
        float w3 = str[r * 64 + 4 * cg + 3];
        a2[0][0] = fmaf(d0, w0, a2[0][0]); a2[0][1] = fmaf(d0, w1, a2[0][1]);
        a2[0][2] = fmaf(d0, w2, a2[0][2]); a2[0][3] = fmaf(d0, w3, a2[0][3]);
        a2[1][0] = fmaf(d1, w0, a2[1][0]); a2[1][1] = fmaf(d1, w1, a2[1][1]);
        a2[1][2] = fmaf(d1, w2, a2[1][2]); a2[1][3] = fmaf(d1, w3, a2[1][3]);
        a2[2][0] = fmaf(d2, w0, a2[2][0]); a2[2][1] = fmaf(d2, w1, a2[2][1]);
        a2[2][2] = fmaf(d2, w2, a2[2][2]); a2[2][3] = fmaf(d2, w3, a2[2][3]);
        a2[3][0] = fmaf(d3, w0, a2[3][0]); a2[3][1] = fmaf(d3, w1, a2[3][1]);
        a2[3][2] = fmaf(d3, w2, a2[3][2]); a2[3][3] = fmaf(d3, w3, a2[3][3]);
    }
#pragma unroll
    for (int i = 0; i < 4; i++) {
        int grow = base + 4 * rg + i;
        float4 v = make_float4(a2[i][0], a2[i][1], a2[i][2], a2[i][3]);
        *(float4*)(g_delta + (size_t)grow * NN + 4 * cg) = v;
    }
}

// ---------------------------------------------------------------------------
// Stage 2: sequential scan. 256 independent chains (b,n), one per thread.
// s_{t+1} = silu(d_t + s_t) + p_t ;  silu(y) = y / (1 + exp(-y))
// Double-buffered loads keep memory off the 48-cycle dependent chain.
// ---------------------------------------------------------------------------
__device__ __forceinline__ float fast_ex2(float v) {
    float r;
    asm("ex2.approx.f32 %0, %1;" : "=f"(r) : "f"(v));
    return r;
}
__device__ __forceinline__ float fast_rcp(float v) {
    float r;
    asm("rcp.approx.f32 %0, %1;" : "=f"(r) : "f"(v));
    return r;
}

__global__ void scan_kernel()
{
    const int chain = blockIdx.x * 32 + threadIdx.x;   // 8 blocks x 32 threads
    const int b = chain >> 6;
    const int n = chain & 63;
    const float* pd = g_delta + (size_t)b * TT * NN + n;
    const float* pp = g_proj + (size_t)b * TT * NN + n;
    float* ps = g_states + (size_t)b * TT * NN + n;

    const float NL2E = -1.4426950408889634f;  // -log2(e)
    float s = 0.f;

    float dA[8], pA[8];
#pragma unroll
    for (int i = 0; i < 8; i++) {
        dA[i] = pd[i * NN];
        pA[i] = pp[i * NN];
    }

    for (int t0 = 0; t0 < TT; t0 += 8) {
        float dB[8], pB[8];
        int tn = t0 + 8;
        if (tn < TT) {
#pragma unroll
            for (int i = 0; i < 8; i++) {
                dB[i] = pd[(tn + i) * NN];
                pB[i] = pp[(tn + i) * NN];
            }
        } else {
#pragma unroll
            for (int i = 0; i < 8; i++) { dB[i] = 0.f; pB[i] = 0.f; }
        }
#pragma unroll
        for (int i = 0; i < 8; i++) {
            float y = s + dA[i];
            float e = fast_ex2(NL2E * y);     // exp(-y)
            float r = fast_rcp(1.f + e);      // sigmoid(y)
            s = fmaf(y, r, pA[i]);            // silu(y) + p
            ps[(t0 + i) * NN] = s;
        }
#pragma unroll
        for (int i = 0; i < 8; i++) { dA[i] = dB[i]; pA[i] = pB[i]; }
    }
}

// ---------------------------------------------------------------------------
// Stage 3: out = states @ out_w^T + out_b.  [16384,64] @ [64,1024].
// 64x64 tiles, K=64 single chunk, classic register-blocked SGEMM.
// ---------------------------------------------------------------------------
__global__ __launch_bounds__(256) void stage3_kernel(
    const float* __restrict__ out_w,
    const float* __restrict__ out_b,
    float* __restrict__ out)
{
    __shared__ float sA[64 * 68];  // [n][row]
    __shared__ float sB[64 * 68];  // [n][col]

    const int tid = threadIdx.x;
    const int rbase = blockIdx.y * 64;
    const int cbase = blockIdx.x * 64;

    for (int idx = tid; idx < 1024; idx += 256) {
        int r = idx >> 4, nq = idx & 15;
        float4 v = *(const float4*)(g_states + (size_t)(rbase + r) * NN + 4 * nq);
        sA[(4 * nq + 0) * 68 + r] = v.x;
        sA[(4 * nq + 1) * 68 + r] = v.y;
        sA[(4 * nq + 2) * 68 + r] = v.z;
        sA[(4 * nq + 3) * 68 + r] = v.w;
    }
    for (int idx = tid; idx < 1024; idx += 256) {
        int c = idx >> 4, nq = idx & 15;
        float4 v = *(const float4*)(out_w + (size_t)(cbase + c) * NN + 4 * nq);
        sB[(4 * nq + 0) * 68 + c] = v.x;
        sB[(4 * nq + 1) * 68 + c] = v.y;
        sB[(4 * nq + 2) * 68 + c] = v.z;
        sB[(4 * nq + 3) * 68 + c] = v.w;
    }
    __syncthreads();

    const int cg = tid & 15;   // col group (coalesced stores)
    const int rg = tid >> 4;   // row group
    float acc[4][4];
#pragma unroll
    for (int i = 0; i < 4; i++)
#pragma unroll
        for (int j = 0; j < 4; j++) acc[i][j] = 0.f;

#pragma unroll 16
    for (int nn = 0; nn < 64; nn++) {
        float4 av = *(float4*)(sA + nn * 68 + 4 * rg);
        float4 bv = *(float4*)(sB + nn * 68 + 4 * cg);
        float a0 = av.x, a1 = av.y, a2 = av.z, a3 = av.w;
        float b0 = bv.x, b1 = bv.y, b2 = bv.z, b3 = bv.w;
        acc[0][0] = fmaf(a0, b0, acc[0][0]); acc[0][1] = fmaf(a0, b1, acc[0][1]);
        acc[0][2] = fmaf(a0, b2, acc[0][2]); acc[0][3] = fmaf(a0, b3, acc[0][3]);
        acc[1][0] = fmaf(a1, b0, acc[1][0]); acc[1][1] = fmaf(a1, b1, acc[1][1]);
        acc[1][2] = fmaf(a1, b2, acc[1][2]); acc[1][3] = fmaf(a1, b3, acc[1][3]);
        acc[2][0] = fmaf(a2, b0, acc[2][0]); acc[2][1] = fmaf(a2, b1, acc[2][1]);
        acc[2][2] = fmaf(a2, b2, acc[2][2]); acc[2][3] = fmaf(a2, b3, acc[2][3]);
        acc[3][0] = fmaf(a3, b0, acc[3][0]); acc[3][1] = fmaf(a3, b1, acc[3][1]);
        acc[3][2] = fmaf(a3, b2, acc[3][2]); acc[3][3] = fmaf(a3, b3, acc[3][3]);
    }

    float4 bb = *(const float4*)(out_b + cbase + 4 * cg);
#pragma unroll
    for (int i = 0; i < 4; i++) {
        float4 v = make_float4(acc[i][0] + bb.x, acc[i][1] + bb.y,
                               acc[i][2] + bb.z, acc[i][3] + bb.w);
        *(float4*)(out + (size_t)(rbase + 4 * rg + i) * DD + cbase + 4 * cg) = v;
    }
}

// ---------------------------------------------------------------------------
extern "C" void kernel_launch(void* const* d_in, const int* in_sizes, int n_in,
                              void* d_out, int out_size)
{
    const float* x      = (const float*)d_in[0];
    const float* conv_w = (const float*)d_in[1];
    const float* in_w   = (const float*)d_in[2];
    const float* in_b   = (const float*)d_in[3];
    const float* dt_w   = (const float*)d_in[4];
    const float* dt_b   = (const float*)d_in[5];
    const float* tr_w   = (const float*)d_in[6];
    const float* out_w  = (const float*)d_in[7];
    const float* out_b  = (const float*)d_in[8];
    float* out = (float*)d_out;

    stage1_kernel<<<256, 256>>>(x, conv_w, in_w, in_b, dt_w, dt_b, tr_w);
    scan_kernel<<<8, 32>>>();
    stage3_kernel<<<dim3(16, 256), 256>>>(out_w, out_b, out);
}

// round 3
// speedup vs baseline: 1.0949x; 1.0949x over previous
#include <cuda_runtime.h>
#include <cstddef>

#define BB 4
#define TT 4096
#define DD 1024
#define NN 64
#define RR 16
#define KK 4
#define BT (BB * TT)

// Scratch (device globals — no allocation allowed)
__device__ float g_mid[4 * BT * 80];   // split-K partials: [kc][row][80]
__device__ float g_proj[BT * NN];
__device__ float g_delta[BT * NN];
__device__ float g_states[BT * NN];

// ---------------------------------------------------------------------------
// Stage 1a: split-K GEMM partials.
//   mid[:,0:64]  = (x + causal_conv(x)) @ in_w^T   (partial over K-chunk)
//   mid[:,64:80] = x @ dt_w^T                      (partial over K-chunk)
// grid (4, 256): blockIdx.x = K-chunk (256 wide), blockIdx.y = 64-row tile.
// ---------------------------------------------------------------------------
__global__ __launch_bounds__(256) void stage1a_kernel(
    const float* __restrict__ x,
    const float* __restrict__ conv_w,
    const float* __restrict__ in_w,
    const float* __restrict__ dt_w)
{
    __shared__ float xs[32 * 72];   // [k][row]; rows 64..66 = halo t0-3..t0-1
    __shared__ float as[32 * 72];   // x + conv tile
    __shared__ float wb[32 * 80];   // [k][c]: c<64 -> in_w, c>=64 -> dt_w
    __shared__ float scw[32 * 4];   // conv_w chunk

    const int tid = threadIdx.x;
    const int koff = blockIdx.x * 256;
    const int base = blockIdx.y * 64;        // global row (b*T + t)
    const int t0 = base & (TT - 1);          // t within batch
    const int cg = tid & 15;                 // column group (0..15)
    const int rg = tid >> 4;                 // row group (0..15)

    float acc[4][5];
#pragma unroll
    for (int i = 0; i < 4; i++)
#pragma unroll
        for (int m = 0; m < 5; m++) acc[i][m] = 0.f;

    for (int k0 = koff; k0 < koff + 256; k0 += 32) {
        // ---- load x tile (67 rows x 32 cols), transposed into xs[k][row] ----
        for (int idx = tid; idx < 67 * 8; idx += 256) {
            int ri = idx >> 3, kq = idx & 7;
            int t = (ri < 64) ? (t0 + ri) : (t0 + ri - 67);  // 64..66 -> t0-3..t0-1
            float4 v = make_float4(0.f, 0.f, 0.f, 0.f);
            if (t >= 0) {
                v = *(const float4*)(x + (size_t)(base - t0 + t) * DD + k0 + 4 * kq);
            }
            int kk = 4 * kq;
            xs[(kk + 0) * 72 + ri] = v.x;
            xs[(kk + 1) * 72 + ri] = v.y;
            xs[(kk + 2) * 72 + ri] = v.z;
            xs[(kk + 3) * 72 + ri] = v.w;
        }
        // ---- load weights: wb[k][c] ----
        for (int idx = tid; idx < 80 * 32; idx += 256) {
            int c = idx >> 5, kk = idx & 31;
            float w = (c < 64) ? in_w[(size_t)c * DD + k0 + kk]
                               : dt_w[(size_t)(c - 64) * DD + k0 + kk];
            wb[kk * 80 + c] = w;
        }
        // ---- load conv_w chunk ----
        if (tid < 128) {
            int kk = tid >> 2, j = tid & 3;
            scw[kk * 4 + j] = conv_w[(size_t)(k0 + kk) * KK + j];
        }
        __syncthreads();

        // ---- build conv A-tile ----
        for (int idx = tid; idx < 32 * 64; idx += 256) {
            int kk = idx >> 6, r = idx & 63;
            const float* xr = xs + kk * 72;
            float c0 = scw[kk * 4 + 0], c1 = scw[kk * 4 + 1];
            float c2 = scw[kk * 4 + 2], c3 = scw[kk * 4 + 3];
            int rm1 = r - 1; if (rm1 < 0) rm1 += 67;
            int rm2 = r - 2; if (rm2 < 0) rm2 += 67;
            int rm3 = r - 3; if (rm3 < 0) rm3 += 67;
            float v = xr[r];
            v = fmaf(c3, xr[r], v);
            v = fmaf(c2, xr[rm1], v);
            v = fmaf(c1, xr[rm2], v);
            v = fmaf(c0, xr[rm3], v);
            as[kk * 72 + r] = v;
        }
        __syncthreads();

        // ---- FFMA main loop ----
#pragma unroll 8
        for (int kk = 0; kk < 32; kk++) {
            float4 av = *(float4*)(as + kk * 72 + 4 * rg);
            float4 xv = *(float4*)(xs + kk * 72 + 4 * rg);
            float b0 = wb[kk * 80 + cg];
            float b1 = wb[kk * 80 + cg + 16];
            float b2 = wb[kk * 80 + cg + 32];
            float b3 = wb[kk * 80 + cg + 48];
            float b4 = wb[kk * 80 + cg + 64];
            float a0 = av.x, a1 = av.y, a2 = av.z, a3 = av.w;
            float x0 = xv.x, x1 = xv.y, x2 = xv.z, x3 = xv.w;
            acc[0][0] = fmaf(a0, b0, acc[0][0]);
            acc[1][0] = fmaf(a1, b0, acc[1][0]);
            acc[2][0] = fmaf(a2, b0, acc[2][0]);
            acc[3][0] = fmaf(a3, b0, acc[3][0]);
            acc[0][1] = fmaf(a0, b1, acc[0][1]);
            acc[1][1] = fmaf(a1, b1, acc[1][1]);
            acc[2][1] = fmaf(a2, b1, acc[2][1]);
            acc[3][1] = fmaf(a3, b1, acc[3][1]);
            acc[0][2] = fmaf(a0, b2, acc[0][2]);
            acc[1][2] = fmaf(a1, b2, acc[1][2]);
            acc[2][2] = fmaf(a2, b2, acc[2][2]);
            acc[3][2] = fmaf(a3, b2, acc[3][2]);
            acc[0][3] = fmaf(a0, b3, acc[0][3]);
            acc[1][3] = fmaf(a1, b3, acc[1][3]);
            acc[2][3] = fmaf(a2, b3, acc[2][3]);
            acc[3][3] = fmaf(a3, b3, acc[3][3]);
            acc[0][4] = fmaf(x0, b4, acc[0][4]);
            acc[1][4] = fmaf(x1, b4, acc[1][4]);
            acc[2][4] = fmaf(x2, b4, acc[2][4]);
            acc[3][4] = fmaf(x3, b4, acc[3][4]);
        }
        __syncthreads();
    }

    // ---- write partials ----
    float* mid = g_mid + (size_t)blockIdx.x * BT * 80;
#pragma unroll
    for (int i = 0; i < 4; i++) {
        size_t row = base + 4 * rg + i;
#pragma unroll
        for (int m = 0; m < 4; m++) {
            mid[row * 80 + cg + 16 * m] = acc[i][m];
        }
        mid[row * 80 + 64 + cg] = acc[i][4];
    }
}

// ---------------------------------------------------------------------------
// Stage 1b: reduce partials, add biases, tanh, tiny tr_w GEMM.
// grid 256, block 256, one 64-row tile per block.
// ---------------------------------------------------------------------------
__global__ __launch_bounds__(256) void stage1b_kernel(
    const float* __restrict__ in_b,
    const float* __restrict__ dt_b,
    const float* __restrict__ tr_w)
{
    __shared__ float sdm[64 * 16];
    __shared__ float str[16 * 64];

    const int tid = threadIdx.x;
    const int base = blockIdx.x * 64;
    const int cg = tid & 15;
    const int rg = tid >> 4;

    for (int idx = tid; idx < NN * RR; idx += 256) {
        int n = idx >> 4, r = idx & 15;
        str[r * 64 + n] = tr_w[idx];
    }

    float dtb = dt_b[cg];
#pragma unroll
    for (int i = 0; i < 4; i++) {
        size_t row = base + 4 * rg + i;
#pragma unroll
        for (int m = 0; m < 4; m++) {
            int c = cg + 16 * m;
            float v = in_b[c];
#pragma unroll
            for (int kc = 0; kc < 4; kc++)
                v += g_mid[((size_t)kc * BT + row) * 80 + c];
            g_proj[row * 64 + c] = v;
        }
        float dm = dtb;
#pragma unroll
        for (int kc = 0; kc < 4; kc++)
            dm += g_mid[((size_t)kc * BT + row) * 80 + 64 + cg];
        sdm[(4 * rg + i) * 16 + cg] = tanhf(dm);
    }
    __syncthreads();

    float a2[4][4];
#pragma unroll
    for (int i = 0; i < 4; i++)
#pragma unroll
        for (int j = 0; j < 4; j++) a2[i][j] = 0.f;
#pragma unroll
    for (int r = 0; r < 16; r++) {
        float d0 = sdm[(4 * rg + 0) * 16 + r];
        float d1 = sdm[(4 * rg + 1) * 16 + r];
        float d2 = sdm[(4 * rg + 2) * 16 + r];
        float d3 = sdm[(4 * rg + 3) * 16 + r];
        float w0 = str[r * 64 + 4 * cg + 0];
        float w1 = str[r * 64 + 4 * cg + 1];
        float w2 = str[r * 64 + 4 * cg + 2];
        float w3 = str[r * 64 + 4 * cg + 3];
        a2[0][0] = fmaf(d0, w0, a2[0][0]); a2[0][1] = fmaf(d0, w1, a2[0][1]);
        a2[0][2] = fmaf(d0, w2, a2[0][2]); a2[0][3] = fmaf(d0, w3, a2[0][3]);
        a2[1][0] = fmaf(d1, w0, a2[1][0]); a2[1][1] = fmaf(d1, w1, a2[1][1]);
        a2[1][2] = fmaf(d1, w2, a2[1][2]); a2[1][3] = fmaf(d1, w3, a2[1][3]);
        a2[2][0] = fmaf(d2, w0, a2[2][0]); a2[2][1] = fmaf(d2, w1, a2[2][1]);
        a2[2][2] = fmaf(d2, w2, a2[2][2]); a2[2][3] = fmaf(d2, w3, a2[2][3]);
        a2[3][0] = fmaf(d3, w0, a2[3][0]); a2[3][1] = fmaf(d3, w1, a2[3][1]);
        a2[3][2] = fmaf(d3, w2, a2[3][2]); a2[3][3] = fmaf(d3, w3, a2[3][3]);
    }
#pragma unroll
    for (int i = 0; i < 4; i++) {
        size_t row = base + 4 * rg + i;
        float4 v = make_float4(a2[i][0], a2[i][1], a2[i][2], a2[i][3]);
        *(float4*)(g_delta + row * NN + 4 * cg) = v;
    }
}

// ---------------------------------------------------------------------------
// Stage 2: sequential scan, 256 chains, 44-cycle dependent chain.
// s' = silu(s + d) + p = y*sigmoid(y) + p,  y = s + d
// Chain: FFMA(ny) -> EX2 -> FADD -> RCP -> FFMA ; y computed off-chain.
// ---------------------------------------------------------------------------
__device__ __forceinline__ float fast_ex2(float v) {
    float r;
    asm("ex2.approx.f32 %0, %1;" : "=f"(r) : "f"(v));
    return r;
}
__device__ __forceinline__ float fast_rcp(float v) {
    float r;
    asm("rcp.approx.f32 %0, %1;" : "=f"(r) : "f"(v));
    return r;
}

__global__ void scan_kernel()
{
    const int chain = blockIdx.x * 32 + threadIdx.x;   // 8 blocks x 32 threads
    const int b = chain >> 6;
    const int n = chain & 63;
    const float* pd = g_delta + (size_t)b * TT * NN + n;
    const float* pp = g_proj + (size_t)b * TT * NN + n;
    float* ps = g_states + (size_t)b * TT * NN + n;

    const float NL2E = -1.4426950408889634f;  // -log2(e)
    float s = 0.f;

    float dA[8], pA[8], ndA[8];
#pragma unroll
    for (int i = 0; i < 8; i++) {
        dA[i] = pd[i * NN];
        pA[i] = pp[i * NN];
        ndA[i] = NL2E * dA[i];
    }

    for (int t0 = 0; t0 < TT; t0 += 8) {
        float dB[8], pB[8];
        int tn = t0 + 8;
        if (tn < TT) {
#pragma unroll
            for (int i = 0; i < 8; i++) {
                dB[i] = pd[(tn + i) * NN];
                pB[i] = pp[(tn + i) * NN];
            }
        } else {
#pragma unroll
            for (int i = 0; i < 8; i++) { dB[i] = 0.f; pB[i] = 0.f; }
        }
#pragma unroll
        for (int i = 0; i < 8; i++) {
            float ny = fmaf(s, NL2E, ndA[i]);  // chain +4
            float e = fast_ex2(ny);            // +16 : exp(-y)
            float den = 1.f + e;               // +4
            float r = fast_rcp(den);           // +16 : sigmoid(y)
            float y = s + dA[i];               // off-chain (parallel)
            s = fmaf(y, r, pA[i]);             // +4
            ps[(t0 + i) * NN] = s;
        }
#pragma unroll
        for (int i = 0; i < 8; i++) {
            dA[i] = dB[i]; pA[i] = pB[i]; ndA[i] = NL2E * dB[i];
        }
    }
}

// ---------------------------------------------------------------------------
// Stage 3: out = states @ out_w^T + out_b.  [16384,64] @ [64,1024].
// 128x128 tiles, K=64, 8x8 fragments, 256 threads. Dynamic smem (67.6 KB).
// ---------------------------------------------------------------------------
#define S3P 132   // smem pitch (floats), 16B-aligned

__global__ __launch_bounds__(256) void stage3_kernel(
    const float* __restrict__ out_w,
    const float* __restrict__ out_b,
    float* __restrict__ out)
{
    extern __shared__ float smem3[];
    float* sA = smem3;              // [k=64][row=128] pitch S3P
    float* sB = smem3 + 64 * S3P;   // [k=64][col=128] pitch S3P

    const int tid = threadIdx.x;
    const int rbase = blockIdx.y * 128;
    const int cbase = blockIdx.x * 128;
    const int tc = tid & 15;   // col group
    const int tr = tid >> 4;   // row group

    // fill A: g_states[(rbase+r)][n] -> sA[n][r]
    for (int idx = tid; idx < 128 * 16; idx += 256) {
        int r = idx >> 4, nq = idx & 15;
        float4 v = *(const float4*)(g_states + (size_t)(rbase + r) * NN + 4 * nq);
        sA[(4 * nq + 0) * S3P + r] = v.x;
        sA[(4 * nq + 1) * S3P + r] = v.y;
        sA[(4 * nq + 2) * S3P + r] = v.z;
        sA[(4 * nq + 3) * S3P + r] = v.w;
    }
    // fill B: out_w[(cbase+c)][n] -> sB[n][c]
    for (int idx = tid; idx < 128 * 16; idx += 256) {
        int c = idx >> 4, nq = idx & 15;
        float4 v = *(const float4*)(out_w + (size_t)(cbase + c) * NN + 4 * nq);
        sB[(4 * nq + 0) * S3P + c] = v.x;
        sB[(4 * nq + 1) * S3P + c] = v.y;
        sB[(4 * nq + 2) * S3P + c] = v.z;
        sB[(4 * nq + 3) * S3P + c] = v.w;
    }
    __syncthreads();

    float acc[8][8];
#pragma unroll
    for (int i = 0; i < 8; i++)
#pragma unroll
        for (int j = 0; j < 8; j++) acc[i][j] = 0.f;

#pragma unroll 8
    for (int k = 0; k < 64; k++) {
        float4 a0 = *(float4*)(sA + k * S3P + 8 * tr);
        float4 a1 = *(float4*)(sA + k * S3P + 8 * tr + 4);
        float4 b0 = *(float4*)(sB + k * S3P + 8 * tc);
        float4 b1 = *(float4*)(sB + k * S3P + 8 * tc + 4);
        float a[8] = {a0.x, a0.y, a0.z, a0.w, a1.x, a1.y, a1.z, a1.w};
        float b[8] = {b0.x, b0.y, b0.z, b0.w, b1.x, b1.y, b1.z, b1.w};
#pragma unroll
        for (int i = 0; i < 8; i++)
#pragma unroll
            for (int j = 0; j < 8; j++)
                acc[i][j] = fmaf(a[i], b[j], acc[i][j]);
    }

    float4 bb0 = *(const float4*)(out_b + cbase + 8 * tc);
    float4 bb1 = *(const float4*)(out_b + cbase + 8 * tc + 4);
#pragma unroll
    for (int i = 0; i < 8; i++) {
        size_t row = rbase + 8 * tr + i;
        float4 v0 = make_float4(acc[i][0] + bb0.x, acc[i][1] + bb0.y,
                                acc[i][2] + bb0.z, acc[i][3] + bb0.w);
        float4 v1 = make_float4(acc[i][4] + bb1.x, acc[i][5] + bb1.y,
                                acc[i][6] + bb1.z, acc[i][7] + bb1.w);
        *(float4*)(out + row * DD + cbase + 8 * tc) = v0;
        *(float4*)(out + row * DD + cbase + 8 * tc + 4) = v1;
    }
}

// ---------------------------------------------------------------------------
extern "C" void kernel_launch(void* const* d_in, const int* in_sizes, int n_in,
                              void* d_out, int out_size)
{
    const float* x      = (const float*)d_in[0];
    const float* conv_w = (const float*)d_in[1];
    const float* in_w   = (const float*)d_in[2];
    const float* in_b   = (const float*)d_in[3];
    const float* dt_w   = (const float*)d_in[4];
    const float* dt_b   = (const float*)d_in[5];
    const float* tr_w   = (const float*)d_in[6];
    const float* out_w  = (const float*)d_in[7];
    const float* out_b  = (const float*)d_in[8];
    float* out = (float*)d_out;

    const int s3_smem = 2 * 64 * S3P * sizeof(float);  // 67584 B
    cudaFuncSetAttribute(stage3_kernel,
                         cudaFuncAttributeMaxDynamicSharedMemorySize, s3_smem);

    stage1a_kernel<<<dim3(4, 256), 256>>>(x, conv_w, in_w, dt_w);
    stage1b_kernel<<<256, 256>>>(in_b, dt_b, tr_w);
    scan_kernel<<<8, 32>>>();
    stage3_kernel<<<dim3(8, 128), 256, s3_smem>>>(out_w, out_b, out);
}

// round 4
// speedup vs baseline: 1.2702x; 1.1601x over previous
#include <cuda_runtime.h>
#include <cstddef>

#define BB 4
#define TT 4096
#define DD 1024
#define NN 64
#define RR 16
#define KK 4
#define BT (BB * TT)

// Scratch (device globals — no allocation allowed)
__device__ float g_mid[4 * BT * 80];   // split-K partials: [kc][row][80]
__device__ float g_proj[BT * NN];
__device__ float g_delta[BT * NN];
__device__ float g_states[BT * NN];

// ---------------------------------------------------------------------------
// Stage 1a: split-K GEMM partials.
//   mid[:,0:64]  = (x + causal_conv(x)) @ in_w^T   (partial over K-chunk)
//   mid[:,64:80] = x @ dt_w^T                      (partial over K-chunk)
// grid (4, 256): blockIdx.x = K-chunk (256 wide), blockIdx.y = 64-row tile.
// ---------------------------------------------------------------------------
__global__ __launch_bounds__(256) void stage1a_kernel(
    const float* __restrict__ x,
    const float* __restrict__ conv_w,
    const float* __restrict__ in_w,
    const float* __restrict__ dt_w)
{
    __shared__ float xs[32 * 72];   // [k][row]; rows 64..66 = halo t0-3..t0-1
    __shared__ float as[32 * 72];   // x + conv tile
    __shared__ float wb[32 * 80];   // [k][c]: c<64 -> in_w, c>=64 -> dt_w
    __shared__ float scw[32 * 4];   // conv_w chunk

    const int tid = threadIdx.x;
    const int koff = blockIdx.x * 256;
    const int base = blockIdx.y * 64;        // global row (b*T + t)
    const int t0 = base & (TT - 1);          // t within batch
    const int cg = tid & 15;                 // column group (0..15)
    const int rg = tid >> 4;                 // row group (0..15)

    float acc[4][5];
#pragma unroll
    for (int i = 0; i < 4; i++)
#pragma unroll
        for (int m = 0; m < 5; m++) acc[i][m] = 0.f;

    for (int k0 = koff; k0 < koff + 256; k0 += 32) {
        // ---- load x tile (67 rows x 32 cols), transposed into xs[k][row] ----
        for (int idx = tid; idx < 67 * 8; idx += 256) {
            int ri = idx >> 3, kq = idx & 7;
            int t = (ri < 64) ? (t0 + ri) : (t0 + ri - 67);  // 64..66 -> t0-3..t0-1
            float4 v = make_float4(0.f, 0.f, 0.f, 0.f);
            if (t >= 0) {
                v = *(const float4*)(x + (size_t)(base - t0 + t) * DD + k0 + 4 * kq);
            }
            int kk = 4 * kq;
            xs[(kk + 0) * 72 + ri] = v.x;
            xs[(kk + 1) * 72 + ri] = v.y;
            xs[(kk + 2) * 72 + ri] = v.z;
            xs[(kk + 3) * 72 + ri] = v.w;
        }
        // ---- load weights: wb[k][c] ----
        for (int idx = tid; idx < 80 * 32; idx += 256) {
            int c = idx >> 5, kk = idx & 31;
            float w = (c < 64) ? in_w[(size_t)c * DD + k0 + kk]
                               : dt_w[(size_t)(c - 64) * DD + k0 + kk];
            wb[kk * 80 + c] = w;
        }
        // ---- load conv_w chunk ----
        if (tid < 128) {
            int kk = tid >> 2, j = tid & 3;
            scw[kk * 4 + j] = conv_w[(size_t)(k0 + kk) * KK + j];
        }
        __syncthreads();

        // ---- build conv A-tile ----
        for (int idx = tid; idx < 32 * 64; idx += 256) {
            int kk = idx >> 6, r = idx & 63;
            const float* xr = xs + kk * 72;
            float c0 = scw[kk * 4 + 0], c1 = scw[kk * 4 + 1];
            float c2 = scw[kk * 4 + 2], c3 = scw[kk * 4 + 3];
            int rm1 = r - 1; if (rm1 < 0) rm1 += 67;
            int rm2 = r - 2; if (rm2 < 0) rm2 += 67;
            int rm3 = r - 3; if (rm3 < 0) rm3 += 67;
            float v = xr[r];
            v = fmaf(c3, xr[r], v);
            v = fmaf(c2, xr[rm1], v);
            v = fmaf(c1, xr[rm2], v);
            v = fmaf(c0, xr[rm3], v);
            as[kk * 72 + r] = v;
        }
        __syncthreads();

        // ---- FFMA main loop ----
#pragma unroll 8
        for (int kk = 0; kk < 32; kk++) {
            float4 av = *(float4*)(as + kk * 72 + 4 * rg);
            float4 xv = *(float4*)(xs + kk * 72 + 4 * rg);
            float b0 = wb[kk * 80 + cg];
            float b1 = wb[kk * 80 + cg + 16];
            float b2 = wb[kk * 80 + cg + 32];
            float b3 = wb[kk * 80 + cg + 48];
            float b4 = wb[kk * 80 + cg + 64];
            float a0 = av.x, a1 = av.y, a2 = av.z, a3 = av.w;
            float x0 = xv.x, x1 = xv.y, x2 = xv.z, x3 = xv.w;
            acc[0][0] = fmaf(a0, b0, acc[0][0]);
            acc[1][0] = fmaf(a1, b0, acc[1][0]);
            acc[2][0] = fmaf(a2, b0, acc[2][0]);
            acc[3][0] = fmaf(a3, b0, acc[3][0]);
            acc[0][1] = fmaf(a0, b1, acc[0][1]);
            acc[1][1] = fmaf(a1, b1, acc[1][1]);
            acc[2][1] = fmaf(a2, b1, acc[2][1]);
            acc[3][1] = fmaf(a3, b1, acc[3][1]);
            acc[0][2] = fmaf(a0, b2, acc[0][2]);
            acc[1][2] = fmaf(a1, b2, acc[1][2]);
            acc[2][2] = fmaf(a2, b2, acc[2][2]);
            acc[3][2] = fmaf(a3, b2, acc[3][2]);
            acc[0][3] = fmaf(a0, b3, acc[0][3]);
            acc[1][3] = fmaf(a1, b3, acc[1][3]);
            acc[2][3] = fmaf(a2, b3, acc[2][3]);
            acc[3][3] = fmaf(a3, b3, acc[3][3]);
            acc[0][4] = fmaf(x0, b4, acc[0][4]);
            acc[1][4] = fmaf(x1, b4, acc[1][4]);
            acc[2][4] = fmaf(x2, b4, acc[2][4]);
            acc[3][4] = fmaf(x3, b4, acc[3][4]);
        }
        __syncthreads();
    }

    // ---- write partials ----
    float* mid = g_mid + (size_t)blockIdx.x * BT * 80;
#pragma unroll
    for (int i = 0; i < 4; i++) {
        size_t row = base + 4 * rg + i;
#pragma unroll
        for (int m = 0; m < 4; m++) {
            mid[row * 80 + cg + 16 * m] = acc[i][m];
        }
        mid[row * 80 + 64 + cg] = acc[i][4];
    }
}

// ---------------------------------------------------------------------------
// Stage 1b: reduce partials, add biases, tanh, tiny tr_w GEMM.
// grid 256, block 256, one 64-row tile per block.
// ---------------------------------------------------------------------------
__global__ __launch_bounds__(256) void stage1b_kernel(
    const float* __restrict__ in_b,
    const float* __restrict__ dt_b,
    const float* __restrict__ tr_w)
{
    __shared__ float sdm[64 * 16];
    __shared__ float str[16 * 64];

    const int tid = threadIdx.x;
    const int base = blockIdx.x * 64;
    const int cg = tid & 15;
    const int rg = tid >> 4;

    for (int idx = tid; idx < NN * RR; idx += 256) {
        int n = idx >> 4, r = idx & 15;
        str[r * 64 + n] = tr_w[idx];
    }

    float dtb = dt_b[cg];
#pragma unroll
    for (int i = 0; i < 4; i++) {
        size_t row = base + 4 * rg + i;
#pragma unroll
        for (int m = 0; m < 4; m++) {
            int c = cg + 16 * m;
            float v = in_b[c];
#pragma unroll
            for (int kc = 0; kc < 4; kc++)
                v += g_mid[((size_t)kc * BT + row) * 80 + c];
            g_proj[row * 64 + c] = v;
        }
        float dm = dtb;
#pragma unroll
        for (int kc = 0; kc < 4; kc++)
            dm += g_mid[((size_t)kc * BT + row) * 80 + 64 + cg];
        sdm[(4 * rg + i) * 16 + cg] = tanhf(dm);
    }
    __syncthreads();

    float a2[4][4];
#pragma unroll
    for (int i = 0; i < 4; i++)
#pragma unroll
        for (int j = 0; j < 4; j++) a2[i][j] = 0.f;
#pragma unroll
    for (int r = 0; r < 16; r++) {
        float d0 = sdm[(4 * rg + 0) * 16 + r];
        float d1 = sdm[(4 * rg + 1) * 16 + r];
        float d2 = sdm[(4 * rg + 2) * 16 + r];
        float d3 = sdm[(4 * rg + 3) * 16 + r];
        float w0 = str[r * 64 + 4 * cg + 0];
        float w1 = str[r * 64 + 4 * cg + 1];
        float w2 = str[r * 64 + 4 * cg + 2];
        float w3 = str[r * 64 + 4 * cg + 3];
        a2[0][0] = fmaf(d0, w0, a2[0][0]); a2[0][1] = fmaf(d0, w1, a2[0][1]);
        a2[0][2] = fmaf(d0, w2, a2[0][2]); a2[0][3] = fmaf(d0, w3, a2[0][3]);
        a2[1][0] = fmaf(d1, w0, a2[1][0]); a2[1][1] = fmaf(d1, w1, a2[1][1]);
        a2[1][2] = fmaf(d1, w2, a2[1][2]); a2[1][3] = fmaf(d1, w3, a2[1][3]);
        a2[2][0] = fmaf(d2, w0, a2[2][0]); a2[2][1] = fmaf(d2, w1, a2[2][1]);
        a2[2][2] = fmaf(d2, w2, a2[2][2]); a2[2][3] = fmaf(d2, w3, a2[2][3]);
        a2[3][0] = fmaf(d3, w0, a2[3][0]); a2[3][1] = fmaf(d3, w1, a2[3][1]);
        a2[3][2] = fmaf(d3, w2, a2[3][2]); a2[3][3] = fmaf(d3, w3, a2[3][3]);
    }
#pragma unroll
    for (int i = 0; i < 4; i++) {
        size_t row = base + 4 * rg + i;
        float4 v = make_float4(a2[i][0], a2[i][1], a2[i][2], a2[i][3]);
        *(float4*)(g_delta + row * NN + 4 * cg) = v;
    }
}

// ---------------------------------------------------------------------------
// Stage 2: sequential scan, 256 chains, 44-cycle dependent chain.
// s' = silu(s + d) + p ; chain FFMA->EX2->FADD->RCP->FFMA = 44 cyc.
// 32-step double buffer: prefetch slack = 32*44 = 1408 cyc > DRAM latency.
// ---------------------------------------------------------------------------
__device__ __forceinline__ float fast_ex2(float v) {
    float r;
    asm("ex2.approx.f32 %0, %1;" : "=f"(r) : "f"(v));
    return r;
}
__device__ __forceinline__ float fast_rcp(float v) {
    float r;
    asm("rcp.approx.f32 %0, %1;" : "=f"(r) : "f"(v));
    return r;
}

#define SG 32   // scan prefetch group size

__global__ void scan_kernel()
{
    const int chain = blockIdx.x * 32 + threadIdx.x;   // 8 blocks x 32 threads
    const int b = chain >> 6;
    const int n = chain & 63;
    const float* pd = g_delta + (size_t)b * TT * NN + n;
    const float* pp = g_proj + (size_t)b * TT * NN + n;
    float* ps = g_states + (size_t)b * TT * NN + n;

    const float NL2E = -1.4426950408889634f;  // -log2(e)
    float s = 0.f;

    float dA[SG], pA[SG];
#pragma unroll
    for (int i = 0; i < SG; i++) {
        dA[i] = pd[i * NN];
        pA[i] = pp[i * NN];
    }

    for (int t0 = 0; t0 < TT; t0 += SG) {
        float dB[SG], pB[SG];
        int tn = t0 + SG;
        if (tn < TT) {
#pragma unroll
            for (int i = 0; i < SG; i++) {
                dB[i] = pd[(tn + i) * NN];
                pB[i] = pp[(tn + i) * NN];
            }
        } else {
#pragma unroll
            for (int i = 0; i < SG; i++) { dB[i] = 0.f; pB[i] = 0.f; }
        }
#pragma unroll
        for (int i = 0; i < SG; i++) {
            float ny = fmaf(s, NL2E, NL2E * dA[i]);  // chain +4 (mul off-chain)
            float e = fast_ex2(ny);                  // +16 : exp(-y)
            float den = 1.f + e;                     // +4
            float r = fast_rcp(den);                 // +16 : sigmoid(y)
            float y = s + dA[i];                     // off-chain (parallel)
            s = fmaf(y, r, pA[i]);                   // +4
            ps[(t0 + i) * NN] = s;
        }
#pragma unroll
        for (int i = 0; i < SG; i++) { dA[i] = dB[i]; pA[i] = pB[i]; }
    }
}

// ---------------------------------------------------------------------------
// Stage 3: out = states @ out_w^T + out_b.  [16384,64] @ [64,1024].
// 128x128 tiles, K=64, 8x8 fragments, 256 threads. Dynamic smem (67.6 KB).
// ---------------------------------------------------------------------------
#define S3P 132   // smem pitch (floats), 16B-aligned

__global__ __launch_bounds__(256) void stage3_kernel(
    const float* __restrict__ out_w,
    const float* __restrict__ out_b,
    float* __restrict__ out)
{
    extern __shared__ float smem3[];
    float* sA = smem3;              // [k=64][row=128] pitch S3P
    float* sB = smem3 + 64 * S3P;   // [k=64][col=128] pitch S3P

    const int tid = threadIdx.x;
    const int rbase = blockIdx.y * 128;
    const int cbase = blockIdx.x * 128;
    const int tc = tid & 15;   // col group
    const int tr = tid >> 4;   // row group

    // fill A: g_states[(rbase+r)][n] -> sA[n][r]
    for (int idx = tid; idx < 128 * 16; idx += 256) {
        int r = idx >> 4, nq = idx & 15;
        float4 v = *(const float4*)(g_states + (size_t)(rbase + r) * NN + 4 * nq);
        sA[(4 * nq + 0) * S3P + r] = v.x;
        sA[(4 * nq + 1) * S3P + r] = v.y;
        sA[(4 * nq + 2) * S3P + r] = v.z;
        sA[(4 * nq + 3) * S3P + r] = v.w;
    }
    // fill B: out_w[(cbase+c)][n] -> sB[n][c]
    for (int idx = tid; idx < 128 * 16; idx += 256) {
        int c = idx >> 4, nq = idx & 15;
        float4 v = *(const float4*)(out_w + (size_t)(cbase + c) * NN + 4 * nq);
        sB[(4 * nq + 0) * S3P + c] = v.x;
        sB[(4 * nq + 1) * S3P + c] = v.y;
        sB[(4 * nq + 2) * S3P + c] = v.z;
        sB[(4 * nq + 3) * S3P + c] = v.w;
    }
    __syncthreads();

    float acc[8][8];
#pragma unroll
    for (int i = 0; i < 8; i++)
#pragma unroll
        for (int j = 0; j < 8; j++) acc[i][j] = 0.f;

#pragma unroll 8
    for (int k = 0; k < 64; k++) {
        float4 a0 = *(float4*)(sA + k * S3P + 8 * tr);
        float4 a1 = *(float4*)(sA + k * S3P + 8 * tr + 4);
        float4 b0 = *(float4*)(sB + k * S3P + 8 * tc);
        float4 b1 = *(float4*)(sB + k * S3P + 8 * tc + 4);
        float a[8] = {a0.x, a0.y, a0.z, a0.w, a1.x, a1.y, a1.z, a1.w};
        float b[8] = {b0.x, b0.y, b0.z, b0.w, b1.x, b1.y, b1.z, b1.w};
#pragma unroll
        for (int i = 0; i < 8; i++)
#pragma unroll
            for (int j = 0; j < 8; j++)
                acc[i][j] = fmaf(a[i], b[j], acc[i][j]);
    }

    float4 bb0 = *(const float4*)(out_b + cbase + 8 * tc);
    float4 bb1 = *(const float4*)(out_b + cbase + 8 * tc + 4);
#pragma unroll
    for (int i = 0; i < 8; i++) {
        size_t row = rbase + 8 * tr + i;
        float4 v0 = make_float4(acc[i][0] + bb0.x, acc[i][1] + bb0.y,
                                acc[i][2] + bb0.z, acc[i][3] + bb0.w);
        float4 v1 = make_float4(acc[i][4] + bb1.x, acc[i][5] + bb1.y,
                                acc[i][6] + bb1.z, acc[i][7] + bb1.w);
        *(float4*)(out + row * DD + cbase + 8 * tc) = v0;
        *(float4*)(out + row * DD + cbase + 8 * tc + 4) = v1;
    }
}

// ---------------------------------------------------------------------------
extern "C" void kernel_launch(void* const* d_in, const int* in_sizes, int n_in,
                              void* d_out, int out_size)
{
    const float* x      = (const float*)d_in[0];
    const float* conv_w = (const float*)d_in[1];
    const float* in_w   = (const float*)d_in[2];
    const float* in_b   = (const float*)d_in[3];
    const float* dt_w   = (const float*)d_in[4];
    const float* dt_b   = (const float*)d_in[5];
    const float* tr_w   = (const float*)d_in[6];
    const float* out_w  = (const float*)d_in[7];
    const float* out_b  = (const float*)d_in[8];
    float* out = (float*)d_out;

    const int s3_smem = 2 * 64 * S3P * sizeof(float);  // 67584 B
    cudaFuncSetAttribute(stage3_kernel,
                         cudaFuncAttributeMaxDynamicSharedMemorySize, s3_smem);

    stage1a_kernel<<<dim3(4, 256), 256>>>(x, conv_w, in_w, dt_w);
    stage1b_kernel<<<256, 256>>>(in_b, dt_b, tr_w);
    scan_kernel<<<8, 32>>>();
    stage3_kernel<<<dim3(8, 128), 256, s3_smem>>>(out_w, out_b, out);
}

// round 5
// speedup vs baseline: 1.3037x; 1.0263x over previous
#include <cuda_runtime.h>
#include <cstddef>

#define BB 4
#define TT 4096
#define DD 1024
#define NN 64
#define RR 16
#define KK 4
#define BT (BB * TT)

// Scratch (device globals — no allocation allowed)
__device__ float g_mid[4 * BT * 80];     // split-K partials: [kc][row][80]
__device__ float2 g_dp[BT * NN];         // interleaved {delta, proj} per (row, n)
__device__ float g_states[BT * NN];

// ---------------------------------------------------------------------------
// Stage 1a: split-K GEMM partials.
//   mid[:,0:64]  = (x + causal_conv(x)) @ in_w^T   (partial over K-chunk)
//   mid[:,64:80] = x @ dt_w^T                      (partial over K-chunk)
// grid (4, 256): blockIdx.x = K-chunk (256 wide), blockIdx.y = 64-row tile.
// ---------------------------------------------------------------------------
__global__ __launch_bounds__(256) void stage1a_kernel(
    const float* __restrict__ x,
    const float* __restrict__ conv_w,
    const float* __restrict__ in_w,
    const float* __restrict__ dt_w)
{
    __shared__ float xs[32 * 72];   // [k][row]; rows 64..66 = halo t0-3..t0-1
    __shared__ float as[32 * 72];   // x + conv tile
    __shared__ float wb[32 * 80];   // [k][c]: c<64 -> in_w, c>=64 -> dt_w
    __shared__ float scw[32 * 4];   // conv_w chunk

    const int tid = threadIdx.x;
    const int koff = blockIdx.x * 256;
    const int base = blockIdx.y * 64;        // global row (b*T + t)
    const int t0 = base & (TT - 1);          // t within batch
    const int cg = tid & 15;                 // column group (0..15)
    const int rg = tid >> 4;                 // row group (0..15)

    float acc[4][5];
#pragma unroll
    for (int i = 0; i < 4; i++)
#pragma unroll
        for (int m = 0; m < 5; m++) acc[i][m] = 0.f;

    for (int k0 = koff; k0 < koff + 256; k0 += 32) {
        // ---- load x tile (67 rows x 32 cols), transposed into xs[k][row] ----
        for (int idx = tid; idx < 67 * 8; idx += 256) {
            int ri = idx >> 3, kq = idx & 7;
            int t = (ri < 64) ? (t0 + ri) : (t0 + ri - 67);  // 64..66 -> t0-3..t0-1
            float4 v = make_float4(0.f, 0.f, 0.f, 0.f);
            if (t >= 0) {
                v = *(const float4*)(x + (size_t)(base - t0 + t) * DD + k0 + 4 * kq);
            }
            int kk = 4 * kq;
            xs[(kk + 0) * 72 + ri] = v.x;
            xs[(kk + 1) * 72 + ri] = v.y;
            xs[(kk + 2) * 72 + ri] = v.z;
            xs[(kk + 3) * 72 + ri] = v.w;
        }
        // ---- load weights: wb[k][c] ----
        for (int idx = tid; idx < 80 * 32; idx += 256) {
            int c = idx >> 5, kk = idx & 31;
            float w = (c < 64) ? in_w[(size_t)c * DD + k0 + kk]
                               : dt_w[(size_t)(c - 64) * DD + k0 + kk];
            wb[kk * 80 + c] = w;
        }
        // ---- load conv_w chunk ----
        if (tid < 128) {
            int kk = tid >> 2, j = tid & 3;
            scw[kk * 4 + j] = conv_w[(size_t)(k0 + kk) * KK + j];
        }
        __syncthreads();

        // ---- build conv A-tile ----
        for (int idx = tid; idx < 32 * 64; idx += 256) {
            int kk = idx >> 6, r = idx & 63;
            const float* xr = xs + kk * 72;
            float c0 = scw[kk * 4 + 0], c1 = scw[kk * 4 + 1];
            float c2 = scw[kk * 4 + 2], c3 = scw[kk * 4 + 3];
            int rm1 = r - 1; if (rm1 < 0) rm1 += 67;
            int rm2 = r - 2; if (rm2 < 0) rm2 += 67;
            int rm3 = r - 3; if (rm3 < 0) rm3 += 67;
            float v = xr[r];
            v = fmaf(c3, xr[r], v);
            v = fmaf(c2, xr[rm1], v);
            v = fmaf(c1, xr[rm2], v);
            v = fmaf(c0, xr[rm3], v);
            as[kk * 72 + r] = v;
        }
        __syncthreads();

        // ---- FFMA main loop ----
#pragma unroll 8
        for (int kk = 0; kk < 32; kk++) {
            float4 av = *(float4*)(as + kk * 72 + 4 * rg);
            float4 xv = *(float4*)(xs + kk * 72 + 4 * rg);
            float b0 = wb[kk * 80 + cg];
            float b1 = wb[kk * 80 + cg + 16];
            float b2 = wb[kk * 80 + cg + 32];
            float b3 = wb[kk * 80 + cg + 48];
            float b4 = wb[kk * 80 + cg + 64];
            float a0 = av.x, a1 = av.y, a2 = av.z, a3 = av.w;
            float x0 = xv.x, x1 = xv.y, x2 = xv.z, x3 = xv.w;
            acc[0][0] = fmaf(a0, b0, acc[0][0]);
            acc[1][0] = fmaf(a1, b0, acc[1][0]);
            acc[2][0] = fmaf(a2, b0, acc[2][0]);
            acc[3][0] = fmaf(a3, b0, acc[3][0]);
            acc[0][1] = fmaf(a0, b1, acc[0][1]);
            acc[1][1] = fmaf(a1, b1, acc[1][1]);
            acc[2][1] = fmaf(a2, b1, acc[2][1]);
            acc[3][1] = fmaf(a3, b1, acc[3][1]);
            acc[0][2] = fmaf(a0, b2, acc[0][2]);
            acc[1][2] = fmaf(a1, b2, acc[1][2]);
            acc[2][2] = fmaf(a2, b2, acc[2][2]);
            acc[3][2] = fmaf(a3, b2, acc[3][2]);
            acc[0][3] = fmaf(a0, b3, acc[0][3]);
            acc[1][3] = fmaf(a1, b3, acc[1][3]);
            acc[2][3] = fmaf(a2, b3, acc[2][3]);
            acc[3][3] = fmaf(a3, b3, acc[3][3]);
            acc[0][4] = fmaf(x0, b4, acc[0][4]);
            acc[1][4] = fmaf(x1, b4, acc[1][4]);
            acc[2][4] = fmaf(x2, b4, acc[2][4]);
            acc[3][4] = fmaf(x3, b4, acc[3][4]);
        }
        __syncthreads();
    }

    // ---- write partials ----
    float* mid = g_mid + (size_t)blockIdx.x * BT * 80;
#pragma unroll
    for (int i = 0; i < 4; i++) {
        size_t row = base + 4 * rg + i;
#pragma unroll
        for (int m = 0; m < 4; m++) {
            mid[row * 80 + cg + 16 * m] = acc[i][m];
        }
        mid[row * 80 + 64 + cg] = acc[i][4];
    }
}

// ---------------------------------------------------------------------------
// Stage 1b: reduce partials, biases, tanh, tr_w GEMM; write interleaved g_dp.
// grid 256, block 256, one 64-row tile per block.
// ---------------------------------------------------------------------------
__global__ __launch_bounds__(256) void stage1b_kernel(
    const float* __restrict__ in_b,
    const float* __restrict__ dt_b,
    const float* __restrict__ tr_w)
{
    __shared__ float sdm[64 * 16];
    __shared__ float str[16 * 64];
    __shared__ float sproj[64 * 68];   // [r][c], pitch 68

    const int tid = threadIdx.x;
    const int base = blockIdx.x * 64;
    const int cg = tid & 15;
    const int rg = tid >> 4;

    for (int idx = tid; idx < NN * RR; idx += 256) {
        int n = idx >> 4, r = idx & 15;
        str[r * 64 + n] = tr_w[idx];
    }

    float dtb = dt_b[cg];
#pragma unroll
    for (int i = 0; i < 4; i++) {
        size_t row = base + 4 * rg + i;
#pragma unroll
        for (int m = 0; m < 4; m++) {
            int c = cg + 16 * m;
            float v = in_b[c];
#pragma unroll
            for (int kc = 0; kc < 4; kc++)
                v += g_mid[((size_t)kc * BT + row) * 80 + c];
            sproj[(4 * rg + i) * 68 + c] = v;
        }
        float dm = dtb;
#pragma unroll
        for (int kc = 0; kc < 4; kc++)
            dm += g_mid[((size_t)kc * BT + row) * 80 + 64 + cg];
        sdm[(4 * rg + i) * 16 + cg] = tanhf(dm);
    }
    __syncthreads();

    float a2[4][4];
#pragma unroll
    for (int i = 0; i < 4; i++)
#pragma unroll
        for (int j = 0; j < 4; j++) a2[i][j] = 0.f;
#pragma unroll
    for (int r = 0; r < 16; r++) {
        float d0 = sdm[(4 * rg + 0) * 16 + r];
        float d1 = sdm[(4 * rg + 1) * 16 + r];
        float d2 = sdm[(4 * rg + 2) * 16 + r];
        float d3 = sdm[(4 * rg + 3) * 16 + r];
        float w0 = str[r * 64 + 4 * cg + 0];
        float w1 = str[r * 64 + 4 * cg + 1];
        float w2 = str[r * 64 + 4 * cg + 2];
        float w3 = str[r * 64 + 4 * cg + 3];
        a2[0][0] = fmaf(d0, w0, a2[0][0]); a2[0][1] = fmaf(d0, w1, a2[0][1]);
        a2[0][2] = fmaf(d0, w2, a2[0][2]); a2[0][3] = fmaf(d0, w3, a2[0][3]);
        a2[1][0] = fmaf(d1, w0, a2[1][0]); a2[1][1] = fmaf(d1, w1, a2[1][1]);
        a2[1][2] = fmaf(d1, w2, a2[1][2]); a2[1][3] = fmaf(d1, w3, a2[1][3]);
        a2[2][0] = fmaf(d2, w0, a2[2][0]); a2[2][1] = fmaf(d2, w1, a2[2][1]);
        a2[2][2] = fmaf(d2, w2, a2[2][2]); a2[2][3] = fmaf(d2, w3, a2[2][3]);
        a2[3][0] = fmaf(d3, w0, a2[3][0]); a2[3][1] = fmaf(d3, w1, a2[3][1]);
        a2[3][2] = fmaf(d3, w2, a2[3][2]); a2[3][3] = fmaf(d3, w3, a2[3][3]);
    }
    // ---- write interleaved {delta, proj} as float4 pairs (2 cols per store) ----
#pragma unroll
    for (int i = 0; i < 4; i++) {
        size_t row = base + 4 * rg + i;
        const float* pr = sproj + (4 * rg + i) * 68 + 4 * cg;
        float4 v0 = make_float4(a2[i][0], pr[0], a2[i][1], pr[1]);
        float4 v1 = make_float4(a2[i][2], pr[2], a2[i][3], pr[3]);
        float* dst = (float*)(g_dp + row * NN + 4 * cg);
        *(float4*)(dst) = v0;
        *(float4*)(dst + 4) = v1;
    }
}

// ---------------------------------------------------------------------------
// Stage 2: sequential scan, 256 chains, 44-cycle dependent chain.
// s' = silu(s + d) + p ; chain FFMA->EX2->FADD->RCP->FFMA = 44 cyc.
// 32-step double buffer of float2 {d,p}: 32 outstanding LDG.64 < M_max(55);
// slack = 32*44 = 1408 cyc > worst-case DRAM latency.
// ---------------------------------------------------------------------------
__device__ __forceinline__ float fast_ex2(float v) {
    float r;
    asm("ex2.approx.f32 %0, %1;" : "=f"(r) : "f"(v));
    return r;
}
__device__ __forceinline__ float fast_rcp(float v) {
    float r;
    asm("rcp.approx.f32 %0, %1;" : "=f"(r) : "f"(v));
    return r;
}

#define SG 32   // scan prefetch group size

__global__ void scan_kernel()
{
    const int chain = blockIdx.x * 32 + threadIdx.x;   // 8 blocks x 32 threads
    const int b = chain >> 6;
    const int n = chain & 63;
    const float2* pdp = g_dp + (size_t)b * TT * NN + n;   // stride NN float2 per t
    float* ps = g_states + (size_t)b * TT * NN + n;

    const float NL2E = -1.4426950408889634f;  // -log2(e)
    float s = 0.f;

    float2 dpA[SG];
#pragma unroll
    for (int i = 0; i < SG; i++) dpA[i] = pdp[i * NN];

    for (int t0 = 0; t0 < TT; t0 += SG) {
        float2 dpB[SG];
        int tn = t0 + SG;
        if (tn < TT) {
#pragma unroll
            for (int i = 0; i < SG; i++) dpB[i] = pdp[(tn + i) * NN];
        } else {
#pragma unroll
            for (int i = 0; i < SG; i++) dpB[i] = make_float2(0.f, 0.f);
        }
#pragma unroll
        for (int i = 0; i < SG; i++) {
            float d = dpA[i].x, p = dpA[i].y;
            float ny = fmaf(s, NL2E, NL2E * d);  // chain +4 (mul off-chain)
            float e = fast_ex2(ny);              // +16 : exp(-y)
            float den = 1.f + e;                 // +4
            float r = fast_rcp(den);             // +16 : sigmoid(y)
            float y = s + d;                     // off-chain (parallel)
            s = fmaf(y, r, p);                   // +4
            ps[(t0 + i) * NN] = s;
        }
#pragma unroll
        for (int i = 0; i < SG; i++) dpA[i] = dpB[i];
    }
}

// ---------------------------------------------------------------------------
// Stage 3: out = states @ out_w^T + out_b.  [16384,64] @ [64,1024].
// 128x128 tiles, K=64, 8x8 fragments, 256 threads. Dynamic smem (67.6 KB).
// ---------------------------------------------------------------------------
#define S3P 132   // smem pitch (floats), 16B-aligned

__global__ __launch_bounds__(256) void stage3_kernel(
    const float* __restrict__ out_w,
    const float* __restrict__ out_b,
    float* __restrict__ out)
{
    extern __shared__ float smem3[];
    float* sA = smem3;              // [k=64][row=128] pitch S3P
    float* sB = smem3 + 64 * S3P;   // [k=64][col=128] pitch S3P

    const int tid = threadIdx.x;
    const int rbase = blockIdx.y * 128;
    const int cbase = blockIdx.x * 128;
    const int tc = tid & 15;   // col group
    const int tr = tid >> 4;   // row group

    // fill A: g_states[(rbase+r)][n] -> sA[n][r]
    for (int idx = tid; idx < 128 * 16; idx += 256) {
        int r = idx >> 4, nq = idx & 15;
        float4 v = *(const float4*)(g_states + (size_t)(rbase + r) * NN + 4 * nq);
        sA[(4 * nq + 0) * S3P + r] = v.x;
        sA[(4 * nq + 1) * S3P + r] = v.y;
        sA[(4 * nq + 2) * S3P + r] = v.z;
        sA[(4 * nq + 3) * S3P + r] = v.w;
    }
    // fill B: out_w[(cbase+c)][n] -> sB[n][c]
    for (int idx = tid; idx < 128 * 16; idx += 256) {
        int c = idx >> 4, nq = idx & 15;
        float4 v = *(const float4*)(out_w + (size_t)(cbase + c) * NN + 4 * nq);
        sB[(4 * nq + 0) * S3P + c] = v.x;
        sB[(4 * nq + 1) * S3P + c] = v.y;
        sB[(4 * nq + 2) * S3P + c] = v.z;
        sB[(4 * nq + 3) * S3P + c] = v.w;
    }
    __syncthreads();

    float acc[8][8];
#pragma unroll
    for (int i = 0; i < 8; i++)
#pragma unroll
        for (int j = 0; j < 8; j++) acc[i][j] = 0.f;

#pragma unroll 8
    for (int k = 0; k < 64; k++) {
        float4 a0 = *(float4*)(sA + k * S3P + 8 * tr);
        float4 a1 = *(float4*)(sA + k * S3P + 8 * tr + 4);
        float4 b0 = *(float4*)(sB + k * S3P + 8 * tc);
        float4 b1 = *(float4*)(sB + k * S3P + 8 * tc + 4);
        float a[8] = {a0.x, a0.y, a0.z, a0.w, a1.x, a1.y, a1.z, a1.w};
        float b[8] = {b0.x, b0.y, b0.z, b0.w, b1.x, b1.y, b1.z, b1.w};
#pragma unroll
        for (int i = 0; i < 8; i++)
#pragma unroll
            for (int j = 0; j < 8; j++)
                acc[i][j] = fmaf(a[i], b[j], acc[i][j]);
    }

    float4 bb0 = *(const float4*)(out_b + cbase + 8 * tc);
    float4 bb1 = *(const float4*)(out_b + cbase + 8 * tc + 4);
#pragma unroll
    for (int i = 0; i < 8; i++) {
        size_t row = rbase + 8 * tr + i;
        float4 v0 = make_float4(acc[i][0] + bb0.x, acc[i][1] + bb0.y,
                                acc[i][2] + bb0.z, acc[i][3] + bb0.w);
        float4 v1 = make_float4(acc[i][4] + bb1.x, acc[i][5] + bb1.y,
                                acc[i][6] + bb1.z, acc[i][7] + bb1.w);
        *(float4*)(out + row * DD + cbase + 8 * tc) = v0;
        *(float4*)(out + row * DD + cbase + 8 * tc + 4) = v1;
    }
}

// ---------------------------------------------------------------------------
extern "C" void kernel_launch(void* const* d_in, const int* in_sizes, int n_in,
                              void* d_out, int out_size)
{
    const float* x      = (const float*)d_in[0];
    const float* conv_w = (const float*)d_in[1];
    const float* in_w   = (const float*)d_in[2];
    const float* in_b   = (const float*)d_in[3];
    const float* dt_w   = (const float*)d_in[4];
    const float* dt_b   = (const float*)d_in[5];
    const float* tr_w   = (const float*)d_in[6];
    const float* out_w  = (const float*)d_in[7];
    const float* out_b  = (const float*)d_in[8];
    float* out = (float*)d_out;

    const int s3_smem = 2 * 64 * S3P * sizeof(float);  // 67584 B
    cudaFuncSetAttribute(stage3_kernel,
                         cudaFuncAttributeMaxDynamicSharedMemorySize, s3_smem);

    stage1a_kernel<<<dim3(4, 256), 256>>>(x, conv_w, in_w, dt_w);
    stage1b_kernel<<<256, 256>>>(in_b, dt_b, tr_w);
    scan_kernel<<<8, 32>>>();
    stage3_kernel<<<dim3(8, 128), 256, s3_smem>>>(out_w, out_b, out);
}

// round 6
// speedup vs baseline: 1.9928x; 1.5286x over previous
#include <cuda_runtime.h>
#include <cstddef>

#define BB 4
#define TT 4096
#define DD 1024
#define NN 64
#define RR 16
#define KK 4
#define BT (BB * TT)
#define SG 32   // scan prefetch group size

// Scratch (device globals — no allocation allowed)
__device__ float g_mid[4 * BT * 80];          // split-K partials: [kc][row][80]
__device__ float2 g_dp[BT * NN + SG * NN];    // interleaved {delta, proj}; padded tail
__device__ float g_states[BT * NN];

// ---------------------------------------------------------------------------
// Stage 1a: split-K GEMM partials.
//   mid[:,0:64]  = (x + causal_conv(x)) @ in_w^T   (partial over K-chunk)
//   mid[:,64:80] = x @ dt_w^T                      (partial over K-chunk)
// grid (4, 256): blockIdx.x = K-chunk (256 wide), blockIdx.y = 64-row tile.
// ---------------------------------------------------------------------------
__global__ __launch_bounds__(256) void stage1a_kernel(
    const float* __restrict__ x,
    const float* __restrict__ conv_w,
    const float* __restrict__ in_w,
    const float* __restrict__ dt_w)
{
    __shared__ float xs[32 * 72];   // [k][row]; rows 64..66 = halo t0-3..t0-1
    __shared__ float as[32 * 72];   // x + conv tile
    __shared__ float wb[32 * 80];   // [k][c]: c<64 -> in_w, c>=64 -> dt_w
    __shared__ float scw[32 * 4];   // conv_w chunk

    const int tid = threadIdx.x;
    const int koff = blockIdx.x * 256;
    const int base = blockIdx.y * 64;        // global row (b*T + t)
    const int t0 = base & (TT - 1);          // t within batch
    const int cg = tid & 15;                 // column group (0..15)
    const int rg = tid >> 4;                 // row group (0..15)

    float acc[4][5];
#pragma unroll
    for (int i = 0; i < 4; i++)
#pragma unroll
        for (int m = 0; m < 5; m++) acc[i][m] = 0.f;

    for (int k0 = koff; k0 < koff + 256; k0 += 32) {
        // ---- load x tile (67 rows x 32 cols), transposed into xs[k][row] ----
        for (int idx = tid; idx < 67 * 8; idx += 256) {
            int ri = idx >> 3, kq = idx & 7;
            int t = (ri < 64) ? (t0 + ri) : (t0 + ri - 67);  // 64..66 -> t0-3..t0-1
            float4 v = make_float4(0.f, 0.f, 0.f, 0.f);
            if (t >= 0) {
                v = *(const float4*)(x + (size_t)(base - t0 + t) * DD + k0 + 4 * kq);
            }
            int kk = 4 * kq;
            xs[(kk + 0) * 72 + ri] = v.x;
            xs[(kk + 1) * 72 + ri] = v.y;
            xs[(kk + 2) * 72 + ri] = v.z;
            xs[(kk + 3) * 72 + ri] = v.w;
        }
        // ---- load weights: wb[k][c] ----
        for (int idx = tid; idx < 80 * 32; idx += 256) {
            int c = idx >> 5, kk = idx & 31;
            float w = (c < 64) ? in_w[(size_t)c * DD + k0 + kk]
                               : dt_w[(size_t)(c - 64) * DD + k0 + kk];
            wb[kk * 80 + c] = w;
        }
        // ---- load conv_w chunk ----
        if (tid < 128) {
            int kk = tid >> 2, j = tid & 3;
            scw[kk * 4 + j] = conv_w[(size_t)(k0 + kk) * KK + j];
        }
        __syncthreads();

        // ---- build conv A-tile ----
        for (int idx = tid; idx < 32 * 64; idx += 256) {
            int kk = idx >> 6, r = idx & 63;
            const float* xr = xs + kk * 72;
            float c0 = scw[kk * 4 + 0], c1 = scw[kk * 4 + 1];
            float c2 = scw[kk * 4 + 2], c3 = scw[kk * 4 + 3];
            int rm1 = r - 1; if (rm1 < 0) rm1 += 67;
            int rm2 = r - 2; if (rm2 < 0) rm2 += 67;
            int rm3 = r - 3; if (rm3 < 0) rm3 += 67;
            float v = xr[r];
            v = fmaf(c3, xr[r], v);
            v = fmaf(c2, xr[rm1], v);
            v = fmaf(c1, xr[rm2], v);
            v = fmaf(c0, xr[rm3], v);
            as[kk * 72 + r] = v;
        }
        __syncthreads();

        // ---- FFMA main loop ----
#pragma unroll 8
        for (int kk = 0; kk < 32; kk++) {
            float4 av = *(float4*)(as + kk * 72 + 4 * rg);
            float4 xv = *(float4*)(xs + kk * 72 + 4 * rg);
            float b0 = wb[kk * 80 + cg];
            float b1 = wb[kk * 80 + cg + 16];
            float b2 = wb[kk * 80 + cg + 32];
            float b3 = wb[kk * 80 + cg + 48];
            float b4 = wb[kk * 80 + cg + 64];
            float a0 = av.x, a1 = av.y, a2 = av.z, a3 = av.w;
            float x0 = xv.x, x1 = xv.y, x2 = xv.z, x3 = xv.w;
            acc[0][0] = fmaf(a0, b0, acc[0][0]);
            acc[1][0] = fmaf(a1, b0, acc[1][0]);
            acc[2][0] = fmaf(a2, b0, acc[2][0]);
            acc[3][0] = fmaf(a3, b0, acc[3][0]);
            acc[0][1] = fmaf(a0, b1, acc[0][1]);
            acc[1][1] = fmaf(a1, b1, acc[1][1]);
            acc[2][1] = fmaf(a2, b1, acc[2][1]);
            acc[3][1] = fmaf(a3, b1, acc[3][1]);
            acc[0][2] = fmaf(a0, b2, acc[0][2]);
            acc[1][2] = fmaf(a1, b2, acc[1][2]);
            acc[2][2] = fmaf(a2, b2, acc[2][2]);
            acc[3][2] = fmaf(a3, b2, acc[3][2]);
            acc[0][3] = fmaf(a0, b3, acc[0][3]);
            acc[1][3] = fmaf(a1, b3, acc[1][3]);
            acc[2][3] = fmaf(a2, b3, acc[2][3]);
            acc[3][3] = fmaf(a3, b3, acc[3][3]);
            acc[0][4] = fmaf(x0, b4, acc[0][4]);
            acc[1][4] = fmaf(x1, b4, acc[1][4]);
            acc[2][4] = fmaf(x2, b4, acc[2][4]);
            acc[3][4] = fmaf(x3, b4, acc[3][4]);
        }
        __syncthreads();
    }

    // ---- write partials ----
    float* mid = g_mid + (size_t)blockIdx.x * BT * 80;
#pragma unroll
    for (int i = 0; i < 4; i++) {
        size_t row = base + 4 * rg + i;
#pragma unroll
        for (int m = 0; m < 4; m++) {
            mid[row * 80 + cg + 16 * m] = acc[i][m];
        }
        mid[row * 80 + 64 + cg] = acc[i][4];
    }
}

// ---------------------------------------------------------------------------
// Stage 1b: reduce partials, biases, tanh, tr_w GEMM; write interleaved g_dp.
// grid 256, block 256, one 64-row tile per block.
// ---------------------------------------------------------------------------
__global__ __launch_bounds__(256) void stage1b_kernel(
    const float* __restrict__ in_b,
    const float* __restrict__ dt_b,
    const float* __restrict__ tr_w)
{
    __shared__ float sdm[64 * 16];
    __shared__ float str[16 * 64];
    __shared__ float sproj[64 * 68];   // [r][c], pitch 68

    const int tid = threadIdx.x;
    const int base = blockIdx.x * 64;
    const int cg = tid & 15;
    const int rg = tid >> 4;

    for (int idx = tid; idx < NN * RR; idx += 256) {
        int n = idx >> 4, r = idx & 15;
        str[r * 64 + n] = tr_w[idx];
    }

    float dtb = dt_b[cg];
#pragma unroll
    for (int i = 0; i < 4; i++) {
        size_t row = base + 4 * rg + i;
#pragma unroll
        for (int m = 0; m < 4; m++) {
            int c = cg + 16 * m;
            float v = in_b[c];
#pragma unroll
            for (int kc = 0; kc < 4; kc++)
                v += g_mid[((size_t)kc * BT + row) * 80 + c];
            sproj[(4 * rg + i) * 68 + c] = v;
        }
        float dm = dtb;
#pragma unroll
        for (int kc = 0; kc < 4; kc++)
            dm += g_mid[((size_t)kc * BT + row) * 80 + 64 + cg];
        sdm[(4 * rg + i) * 16 + cg] = tanhf(dm);
    }
    __syncthreads();

    float a2[4][4];
#pragma unroll
    for (int i = 0; i < 4; i++)
#pragma unroll
        for (int j = 0; j < 4; j++) a2[i][j] = 0.f;
#pragma unroll
    for (int r = 0; r < 16; r++) {
        float d0 = sdm[(4 * rg + 0) * 16 + r];
        float d1 = sdm[(4 * rg + 1) * 16 + r];
        float d2 = sdm[(4 * rg + 2) * 16 + r];
        float d3 = sdm[(4 * rg + 3) * 16 + r];
        float w0 = str[r * 64 + 4 * cg + 0];
        float w1 = str[r * 64 + 4 * cg + 1];
        float w2 = str[r * 64 + 4 * cg + 2];
        float w3 = str[r * 64 + 4 * cg + 3];
        a2[0][0] = fmaf(d0, w0, a2[0][0]); a2[0][1] = fmaf(d0, w1, a2[0][1]);
        a2[0][2] = fmaf(d0, w2, a2[0][2]); a2[0][3] = fmaf(d0, w3, a2[0][3]);
        a2[1][0] = fmaf(d1, w0, a2[1][0]); a2[1][1] = fmaf(d1, w1, a2[1][1]);
        a2[1][2] = fmaf(d1, w2, a2[1][2]); a2[1][3] = fmaf(d1, w3, a2[1][3]);
        a2[2][0] = fmaf(d2, w0, a2[2][0]); a2[2][1] = fmaf(d2, w1, a2[2][1]);
        a2[2][2] = fmaf(d2, w2, a2[2][2]); a2[2][3] = fmaf(d2, w3, a2[2][3]);
        a2[3][0] = fmaf(d3, w0, a2[3][0]); a2[3][1] = fmaf(d3, w1, a2[3][1]);
        a2[3][2] = fmaf(d3, w2, a2[3][2]); a2[3][3] = fmaf(d3, w3, a2[3][3]);
    }
    // ---- write interleaved {delta, proj} as float4 pairs (2 cols per store) ----
#pragma unroll
    for (int i = 0; i < 4; i++) {
        size_t row = base + 4 * rg + i;
        const float* pr = sproj + (4 * rg + i) * 68 + 4 * cg;
        float4 v0 = make_float4(a2[i][0], pr[0], a2[i][1], pr[1]);
        float4 v1 = make_float4(a2[i][2], pr[2], a2[i][3], pr[3]);
        float* dst = (float*)(g_dp + row * NN + 4 * cg);
        *(float4*)(dst) = v0;
        *(float4*)(dst + 4) = v1;
    }
}

// ---------------------------------------------------------------------------
// Stage 2: sequential scan, 256 chains, 24-cycle dependent chain via MUFU.TANH.
// silu(y) = h*(1 + tanh(h)), h = y/2  =>  s' = fmaf(h, tanh(h), h + p)
// chain: FFMA(h) 4 -> TANH 16 -> FFMA 4 = 24 cyc; (h+p) resolves in parallel.
// 32-step double buffer of {d/2, p}: slack 32*24 = 768 cyc >= L2 latency.
// ---------------------------------------------------------------------------
__device__ __forceinline__ float fast_tanh(float v) {
    float r;
    asm("tanh.approx.f32 %0, %1;" : "=f"(r) : "f"(v));
    return r;
}

__global__ __launch_bounds__(32) void scan_kernel()
{
    const int chain = blockIdx.x * 32 + threadIdx.x;   // 8 blocks x 32 threads
    const int b = chain >> 6;
    const int n = chain & 63;
    const float2* pdp = g_dp + (size_t)b * TT * NN + n;   // stride NN float2 per t
    float* ps = g_states + (size_t)b * TT * NN + n;

    float s = 0.f;

    float2 dpA[SG];   // .x = d/2, .y = p
#pragma unroll
    for (int i = 0; i < SG; i++) {
        float2 v = pdp[i * NN];
        dpA[i] = make_float2(0.5f * v.x, v.y);
    }

    for (int t0 = 0; t0 < TT; t0 += SG) {
        float2 dpB[SG];
        int tn = t0 + SG;
        // padded tail: reads past TT land in the pad region, values unused
#pragma unroll
        for (int i = 0; i < SG; i++) dpB[i] = pdp[(tn + i) * NN];
#pragma unroll
        for (int i = 0; i < SG; i++) {
            float hd = dpA[i].x, p = dpA[i].y;
            float h = fmaf(s, 0.5f, hd);     // chain +4
            float th = fast_tanh(h);         // +16
            float hp = h + p;                // off-chain (parallel with tanh)
            s = fmaf(h, th, hp);             // +4
            ps[(t0 + i) * NN] = s;
        }
#pragma unroll
        for (int i = 0; i < SG; i++) {
            dpA[i] = make_float2(0.5f * dpB[i].x, dpB[i].y);
        }
    }
}

// ---------------------------------------------------------------------------
// Stage 3: out = states @ out_w^T + out_b.  [16384,64] @ [64,1024].
// 128x128 tiles, K=64, 8x8 fragments, 256 threads. Dynamic smem (67.6 KB).
// ---------------------------------------------------------------------------
#define S3P 132   // smem pitch (floats), 16B-aligned

__global__ __launch_bounds__(256) void stage3_kernel(
    const float* __restrict__ out_w,
    const float* __restrict__ out_b,
    float* __restrict__ out)
{
    extern __shared__ float smem3[];
    float* sA = smem3;              // [k=64][row=128] pitch S3P
    float* sB = smem3 + 64 * S3P;   // [k=64][col=128] pitch S3P

    const int tid = threadIdx.x;
    const int rbase = blockIdx.y * 128;
    const int cbase = blockIdx.x * 128;
    const int tc = tid & 15;   // col group
    const int tr = tid >> 4;   // row group

    // fill A: g_states[(rbase+r)][n] -> sA[n][r]
    for (int idx = tid; idx < 128 * 16; idx += 256) {
        int r = idx >> 4, nq = idx & 15;
        float4 v = *(const float4*)(g_states + (size_t)(rbase + r) * NN + 4 * nq);
        sA[(4 * nq + 0) * S3P + r] = v.x;
        sA[(4 * nq + 1) * S3P + r] = v.y;
        sA[(4 * nq + 2) * S3P + r] = v.z;
        sA[(4 * nq + 3) * S3P + r] = v.w;
    }
    // fill B: out_w[(cbase+c)][n] -> sB[n][c]
    for (int idx = tid; idx < 128 * 16; idx += 256) {
        int c = idx >> 4, nq = idx & 15;
        float4 v = *(const float4*)(out_w + (size_t)(cbase + c) * NN + 4 * nq);
        sB[(4 * nq + 0) * S3P + c] = v.x;
        sB[(4 * nq + 1) * S3P + c] = v.y;
        sB[(4 * nq + 2) * S3P + c] = v.z;
        sB[(4 * nq + 3) * S3P + c] = v.w;
    }
    __syncthreads();

    float acc[8][8];
#pragma unroll
    for (int i = 0; i < 8; i++)
#pragma unroll
        for (int j = 0; j < 8; j++) acc[i][j] = 0.f;

#pragma unroll 8
    for (int k = 0; k < 64; k++) {
        float4 a0 = *(float4*)(sA + k * S3P + 8 * tr);
        float4 a1 = *(float4*)(sA + k * S3P + 8 * tr + 4);
        float4 b0 = *(float4*)(sB + k * S3P + 8 * tc);
        float4 b1 = *(float4*)(sB + k * S3P + 8 * tc + 4);
        float a[8] = {a0.x, a0.y, a0.z, a0.w, a1.x, a1.y, a1.z, a1.w};
        float b[8] = {b0.x, b0.y, b0.z, b0.w, b1.x, b1.y, b1.z, b1.w};
#pragma unroll
        for (int i = 0; i < 8; i++)
#pragma unroll
            for (int j = 0; j < 8; j++)
                acc[i][j] = fmaf(a[i], b[j], acc[i][j]);
    }

    float4 bb0 = *(const float4*)(out_b + cbase + 8 * tc);
    float4 bb1 = *(const float4*)(out_b + cbase + 8 * tc + 4);
#pragma unroll
    for (int i = 0; i < 8; i++) {
        size_t row = rbase + 8 * tr + i;
        float4 v0 = make_float4(acc[i][0] + bb0.x, acc[i][1] + bb0.y,
                                acc[i][2] + bb0.z, acc[i][3] + bb0.w);
        float4 v1 = make_float4(acc[i][4] + bb1.x, acc[i][5] + bb1.y,
                                acc[i][6] + bb1.z, acc[i][7] + bb1.w);
        *(float4*)(out + row * DD + cbase + 8 * tc) = v0;
        *(float4*)(out + row * DD + cbase + 8 * tc + 4) = v1;
    }
}

// ---------------------------------------------------------------------------
extern "C" void kernel_launch(void* const* d_in, const int* in_sizes, int n_in,
                              void* d_out, int out_size)
{
    const float* x      = (const float*)d_in[0];
    const float* conv_w = (const float*)d_in[1];
    const float* in_w   = (const float*)d_in[2];
    const float* in_b   = (const float*)d_in[3];
    const float* dt_w   = (const float*)d_in[4];
    const float* dt_b   = (const float*)d_in[5];
    const float* tr_w   = (const float*)d_in[6];
    const float* out_w  = (const float*)d_in[7];
    const float* out_b  = (const float*)d_in[8];
    float* out = (float*)d_out;

    const int s3_smem = 2 * 64 * S3P * sizeof(float);  // 67584 B
    cudaFuncSetAttribute(stage3_kernel,
                         cudaFuncAttributeMaxDynamicSharedMemorySize, s3_smem);

    stage1a_kernel<<<dim3(4, 256), 256>>>(x, conv_w, in_w, dt_w);
    stage1b_kernel<<<256, 256>>>(in_b, dt_b, tr_w);
    scan_kernel<<<8, 32>>>();
    stage3_kernel<<<dim3(8, 128), 256, s3_smem>>>(out_w, out_b, out);
}

// round 7
// speedup vs baseline: 2.2557x; 1.1319x over previous
#include <cuda_runtime.h>
#include <cstddef>

#define BB 4
#define TT 4096
#define DD 1024
#define NN 64
#define RR 16
#define KK 4
#define BT (BB * TT)
#define SG 32    // scan prefetch group size

// Scratch (device globals — no allocation allowed)
__device__ float g_mid[4 * 80 * BT];          // split-K partials, [kc][col][row]
__device__ float2 g_dp[BT * NN + SG * NN];    // interleaved {delta, proj}; padded tail
__device__ float g_states[BT * NN];

// ---------------------------------------------------------------------------
// Stage 1a: split-K GEMM partials, 256-row x 80-col tiles, 8x10 fragments.
//   cols 0..63  = (x + causal_conv(x)) @ in_w^T   (partial over K-chunk)
//   cols 64..79 = x @ dt_w^T                      (partial over K-chunk)
// grid (4, 64): blockIdx.x = K-chunk (256 wide), blockIdx.y = 256-row tile.
// Dynamic smem: xs[32][264] (+3 halo rows at 256..258), as[32][264], wb[32][80].
// ---------------------------------------------------------------------------
#define XP 264   // xs/as pitch

__global__ __launch_bounds__(256, 2) void stage1a_kernel(
    const float* __restrict__ x,
    const float* __restrict__ conv_w,
    const float* __restrict__ in_w,
    const float* __restrict__ dt_w)
{
    extern __shared__ float s1[];
    float* xs = s1;                  // 32 * 264
    float* as = s1 + 32 * XP;        // 32 * 264
    float* wb = s1 + 64 * XP;        // 32 * 80, [kk][c]
    float* scw = wb + 32 * 80;       // 32 * 4

    const int tid = threadIdx.x;
    const int koff = blockIdx.x * 256;
    const int base = blockIdx.y * 256;       // global row (b*T + t)
    const int t0 = base & (TT - 1);          // t within batch (tiles never straddle)
    const int cg = tid & 7;                  // col group (0..7)
    const int rg = tid >> 3;                 // row group (0..31), rows 8*rg..8*rg+7

    float acc[8][10];
#pragma unroll
    for (int i = 0; i < 8; i++)
#pragma unroll
        for (int m = 0; m < 10; m++) acc[i][m] = 0.f;

    for (int k0 = koff; k0 < koff + 256; k0 += 32) {
        // ---- load x tile (259 rows x 32 k), transposed into xs[k][row] ----
        for (int idx = tid; idx < 259 * 8; idx += 256) {
            int ri = idx >> 3, kq = idx & 7;
            int t = (ri < 256) ? (t0 + ri) : (t0 + ri - 259);  // 256..258 -> t0-3..t0-1
            float4 v = make_float4(0.f, 0.f, 0.f, 0.f);
            if (t >= 0) {
                v = *(const float4*)(x + (size_t)(base - t0 + t) * DD + k0 + 4 * kq);
            }
            int kk = 4 * kq;
            xs[(kk + 0) * XP + ri] = v.x;
            xs[(kk + 1) * XP + ri] = v.y;
            xs[(kk + 2) * XP + ri] = v.z;
            xs[(kk + 3) * XP + ri] = v.w;
        }
        // ---- load weights: wb[kk][c] ----
        for (int idx = tid; idx < 80 * 32; idx += 256) {
            int c = idx >> 5, kk = idx & 31;
            float w = (c < 64) ? in_w[(size_t)c * DD + k0 + kk]
                               : dt_w[(size_t)(c - 64) * DD + k0 + kk];
            wb[kk * 80 + c] = w;
        }
        // ---- load conv_w chunk ----
        if (tid < 128) {
            int kk = tid >> 2, j = tid & 3;
            scw[kk * 4 + j] = conv_w[(size_t)(k0 + kk) * KK + j];
        }
        __syncthreads();

        // ---- build conv A-tile: as[kk][r] = x[r] + sum_j cw[j]*x[r-3+j] ----
        for (int idx = tid; idx < 32 * 256; idx += 256) {
            int kk = idx >> 8, r = idx & 255;
            const float* xr = xs + kk * XP;
            float c0 = scw[kk * 4 + 0], c1 = scw[kk * 4 + 1];
            float c2 = scw[kk * 4 + 2], c3 = scw[kk * 4 + 3];
            int rm1 = r - 1; if (rm1 < 0) rm1 += 259;
            int rm2 = r - 2; if (rm2 < 0) rm2 += 259;
            int rm3 = r - 3; if (rm3 < 0) rm3 += 259;
            float v = xr[r];
            v = fmaf(c3, xr[r], v);
            v = fmaf(c2, xr[rm1], v);
            v = fmaf(c1, xr[rm2], v);
            v = fmaf(c0, xr[rm3], v);
            as[kk * XP + r] = v;
        }
        __syncthreads();

        // ---- FFMA main loop: 8 rows x (8 conv-cols + 2 dt-cols) ----
#pragma unroll 4
        for (int kk = 0; kk < 32; kk++) {
            float4 av0 = *(float4*)(as + kk * XP + 8 * rg);
            float4 av1 = *(float4*)(as + kk * XP + 8 * rg + 4);
            float4 xv0 = *(float4*)(xs + kk * XP + 8 * rg);
            float4 xv1 = *(float4*)(xs + kk * XP + 8 * rg + 4);
            float a[8] = {av0.x, av0.y, av0.z, av0.w, av1.x, av1.y, av1.z, av1.w};
            float xw[8] = {xv0.x, xv0.y, xv0.z, xv0.w, xv1.x, xv1.y, xv1.z, xv1.w};
            const float* wk = wb + kk * 80;
            float b[8];
#pragma unroll
            for (int m = 0; m < 8; m++) b[m] = wk[cg + 8 * m];
            float bd0 = wk[64 + cg];
            float bd1 = wk[72 + cg];
#pragma unroll
            for (int i = 0; i < 8; i++) {
#pragma unroll
                for (int m = 0; m < 8; m++)
                    acc[i][m] = fmaf(a[i], b[m], acc[i][m]);
                acc[i][8] = fmaf(xw[i], bd0, acc[i][8]);
                acc[i][9] = fmaf(xw[i], bd1, acc[i][9]);
            }
        }
        __syncthreads();
    }

    // ---- write partials, column-major g_mid[kc][c][row], float4 stores ----
    {
        float* mid = g_mid + (size_t)blockIdx.x * 80 * BT;
        size_t row0 = base + 8 * rg;
#pragma unroll
        for (int m = 0; m < 10; m++) {
            int c = (m < 8) ? (cg + 8 * m) : (64 + 8 * (m - 8) + cg);
            float* dst = mid + (size_t)c * BT + row0;
            *(float4*)(dst)     = make_float4(acc[0][m], acc[1][m], acc[2][m], acc[3][m]);
            *(float4*)(dst + 4) = make_float4(acc[4][m], acc[5][m], acc[6][m], acc[7][m]);
        }
    }
}

// ---------------------------------------------------------------------------
// Stage 1b: reduce partials, biases, tanh, tr_w GEMM; write interleaved g_dp.
// grid 256, block 256, one 64-row tile per block. g_mid is [kc][c][row].
// ---------------------------------------------------------------------------
__global__ __launch_bounds__(256) void stage1b_kernel(
    const float* __restrict__ in_b,
    const float* __restrict__ dt_b,
    const float* __restrict__ tr_w)
{
    __shared__ float sdm[64 * 16];
    __shared__ float str[16 * 64];
    __shared__ float sproj[64 * 68];   // [r][c], pitch 68

    const int tid = threadIdx.x;
    const int base = blockIdx.x * 64;
    const int cg = tid & 15;
    const int rg = tid >> 4;

    for (int idx = tid; idx < NN * RR; idx += 256) {
        int n = idx >> 4, r = idx & 15;
        str[r * 64 + n] = tr_w[idx];
    }

    float dtb = dt_b[cg];
#pragma unroll
    for (int i = 0; i < 4; i++) {
        size_t row = base + 4 * rg + i;
#pragma unroll
        for (int m = 0; m < 4; m++) {
            int c = cg + 16 * m;
            float v = in_b[c];
#pragma unroll
            for (int kc = 0; kc < 4; kc++)
                v += g_mid[((size_t)kc * 80 + c) * BT + row];
            sproj[(4 * rg + i) * 68 + c] = v;
        }
        float dm = dtb;
#pragma unroll
        for (int kc = 0; kc < 4; kc++)
            dm += g_mid[((size_t)kc * 80 + 64 + cg) * BT + row];
        sdm[(4 * rg + i) * 16 + cg] = tanhf(dm);
    }
    __syncthreads();

    float a2[4][4];
#pragma unroll
    for (int i = 0; i < 4; i++)
#pragma unroll
        for (int j = 0; j < 4; j++) a2[i][j] = 0.f;
#pragma unroll
    for (int r = 0; r < 16; r++) {
        float d0 = sdm[(4 * rg + 0) * 16 + r];
        float d1 = sdm[(4 * rg + 1) * 16 + r];
        float d2 = sdm[(4 * rg + 2) * 16 + r];
        float d3 = sdm[(4 * rg + 3) * 16 + r];
        float w0 = str[r * 64 + 4 * cg + 0];
        float w1 = str[r * 64 + 4 * cg + 1];
        float w2 = str[r * 64 + 4 * cg + 2];
        float w3 = str[r * 64 + 4 * cg + 3];
        a2[0][0] = fmaf(d0, w0, a2[0][0]); a2[0][1] = fmaf(d0, w1, a2[0][1]);
        a2[0][2] = fmaf(d0, w2, a2[0][2]); a2[0][3] = fmaf(d0, w3, a2[0][3]);
        a2[1][0] = fmaf(d1, w0, a2[1][0]); a2[1][1] = fmaf(d1, w1, a2[1][1]);
        a2[1][2] = fmaf(d1, w2, a2[1][2]); a2[1][3] = fmaf(d1, w3, a2[1][3]);
        a2[2][0] = fmaf(d2, w0, a2[2][0]); a2[2][1] = fmaf(d2, w1, a2[2][1]);
        a2[2][2] = fmaf(d2, w2, a2[2][2]); a2[2][3] = fmaf(d2, w3, a2[2][3]);
        a2[3][0] = fmaf(d3, w0, a2[3][0]); a2[3][1] = fmaf(d3, w1, a2[3][1]);
        a2[3][2] = fmaf(d3, w2, a2[3][2]); a2[3][3] = fmaf(d3, w3, a2[3][3]);
    }
    // ---- write interleaved {delta, proj} as float4 pairs (2 cols per store) ----
#pragma unroll
    for (int i = 0; i < 4; i++) {
        size_t row = base + 4 * rg + i;
        const float* pr = sproj + (4 * rg + i) * 68 + 4 * cg;
        float4 v0 = make_float4(a2[i][0], pr[0], a2[i][1], pr[1]);
        float4 v1 = make_float4(a2[i][2], pr[2], a2[i][3], pr[3]);
        float* dst = (float*)(g_dp + row * NN + 4 * cg);
        *(float4*)(dst) = v0;
        *(float4*)(dst + 4) = v1;
    }
}

// ---------------------------------------------------------------------------
// Stage 2: sequential scan, 256 chains, 24-cycle dependent chain via MUFU.TANH.
// silu(y) = h*(1 + tanh(h)), h = y/2  =>  s' = fmaf(h, tanh(h), h + p)
// ---------------------------------------------------------------------------
__device__ __forceinline__ float fast_tanh(float v) {
    float r;
    asm("tanh.approx.f32 %0, %1;" : "=f"(r) : "f"(v));
    return r;
}

__global__ __launch_bounds__(32) void scan_kernel()
{
    const int chain = blockIdx.x * 32 + threadIdx.x;   // 8 blocks x 32 threads
    const int b = chain >> 6;
    const int n = chain & 63;
    const float2* pdp = g_dp + (size_t)b * TT * NN + n;   // stride NN float2 per t
    float* ps = g_states + (size_t)b * TT * NN + n;

    float s = 0.f;

    float2 dpA[SG];   // .x = d/2, .y = p
#pragma unroll
    for (int i = 0; i < SG; i++) {
        float2 v = pdp[i * NN];
        dpA[i] = make_float2(0.5f * v.x, v.y);
    }

    for (int t0 = 0; t0 < TT; t0 += SG) {
        float2 dpB[SG];
        int tn = t0 + SG;
        // padded tail: reads past TT land in the pad region, values unused
#pragma unroll
        for (int i = 0; i < SG; i++) dpB[i] = pdp[(tn + i) * NN];
#pragma unroll
        for (int i = 0; i < SG; i++) {
            float hd = dpA[i].x, p = dpA[i].y;
            float h = fmaf(s, 0.5f, hd);     // chain +4
            float th = fast_tanh(h);         // +16
            float hp = h + p;                // off-chain (parallel with tanh)
            s = fmaf(h, th, hp);             // +4
            ps[(t0 + i) * NN] = s;
        }
#pragma unroll
        for (int i = 0; i < SG; i++) {
            dpA[i] = make_float2(0.5f * dpB[i].x, dpB[i].y);
        }
    }
}

// ---------------------------------------------------------------------------
// Stage 3: out = states @ out_w^T + out_b.  [16384,64] @ [64,1024].
// 128x128 tiles, K=64, 8x8 fragments, 256 threads. Dynamic smem (67.6 KB).
// ---------------------------------------------------------------------------
#define S3P 132   // smem pitch (floats), 16B-aligned

__global__ __launch_bounds__(256) void stage3_kernel(
    const float* __restrict__ out_w,
    const float* __restrict__ out_b,
    float* __restrict__ out)
{
    extern __shared__ float smem3[];
    float* sA = smem3;              // [k=64][row=128] pitch S3P
    float* sB = smem3 + 64 * S3P;   // [k=64][col=128] pitch S3P

    const int tid = threadIdx.x;
    const int rbase = blockIdx.y * 128;
    const int cbase = blockIdx.x * 128;
    const int tc = tid & 15;   // col group
    const int tr = tid >> 4;   // row group

    // fill A: g_states[(rbase+r)][n] -> sA[n][r]
    for (int idx = tid; idx < 128 * 16; idx += 256) {
        int r = idx >> 4, nq = idx & 15;
        float4 v = *(const float4*)(g_states + (size_t)(rbase + r) * NN + 4 * nq);
        sA[(4 * nq + 0) * S3P + r] = v.x;
        sA[(4 * nq + 1) * S3P + r] = v.y;
        sA[(4 * nq + 2) * S3P + r] = v.z;
        sA[(4 * nq + 3) * S3P + r] = v.w;
    }
    // fill B: out_w[(cbase+c)][n] -> sB[n][c]
    for (int idx = tid; idx < 128 * 16; idx += 256) {
        int c = idx >> 4, nq = idx & 15;
        float4 v = *(const float4*)(out_w + (size_t)(cbase + c) * NN + 4 * nq);
        sB[(4 * nq + 0) * S3P + c] = v.x;
        sB[(4 * nq + 1) * S3P + c] = v.y;
        sB[(4 * nq + 2) * S3P + c] = v.z;
        sB[(4 * nq + 3) * S3P + c] = v.w;
    }
    __syncthreads();

    float acc[8][8];
#pragma unroll
    for (int i = 0; i < 8; i++)
#pragma unroll
        for (int j = 0; j < 8; j++) acc[i][j] = 0.f;

#pragma unroll 8
    for (int k = 0; k < 64; k++) {
        float4 a0 = *(float4*)(sA + k * S3P + 8 * tr);
        float4 a1 = *(float4*)(sA + k * S3P + 8 * tr + 4);
        float4 b0 = *(float4*)(sB + k * S3P + 8 * tc);
        float4 b1 = *(float4*)(sB + k * S3P + 8 * tc + 4);
        float a[8] = {a0.x, a0.y, a0.z, a0.w, a1.x, a1.y, a1.z, a1.w};
        float b[8] = {b0.x, b0.y, b0.z, b0.w, b1.x, b1.y, b1.z, b1.w};
#pragma unroll
        for (int i = 0; i < 8; i++)
#pragma unroll
            for (int j = 0; j < 8; j++)
                acc[i][j] = fmaf(a[i], b[j], acc[i][j]);
    }

    float4 bb0 = *(const float4*)(out_b + cbase + 8 * tc);
    float4 bb1 = *(const float4*)(out_b + cbase + 8 * tc + 4);
#pragma unroll
    for (int i = 0; i < 8; i++) {
        size_t row = rbase + 8 * tr + i;
        float4 v0 = make_float4(acc[i][0] + bb0.x, acc[i][1] + bb0.y,
                                acc[i][2] + bb0.z, acc[i][3] + bb0.w);
        float4 v1 = make_float4(acc[i][4] + bb1.x, acc[i][5] + bb1.y,
                                acc[i][6] + bb1.z, acc[i][7] + bb1.w);
        *(float4*)(out + row * DD + cbase + 8 * tc) = v0;
        *(float4*)(out + row * DD + cbase + 8 * tc + 4) = v1;
    }
}

// ---------------------------------------------------------------------------
extern "C" void kernel_launch(void* const* d_in, const int* in_sizes, int n_in,
                              void* d_out, int out_size)
{
    const float* x      = (const float*)d_in[0];
    const float* conv_w = (const float*)d_in[1];
    const float* in_w   = (const float*)d_in[2];
    const float* in_b   = (const float*)d_in[3];
    const float* dt_w   = (const float*)d_in[4];
    const float* dt_b   = (const float*)d_in[5];
    const float* tr_w   = (const float*)d_in[6];
    const float* out_w  = (const float*)d_in[7];
    const float* out_b  = (const float*)d_in[8];
    float* out = (float*)d_out;

    const int s1_smem = (64 * XP + 32 * 80 + 32 * 4) * sizeof(float);  // 78336 B
    cudaFuncSetAttribute(stage1a_kernel,
                         cudaFuncAttributeMaxDynamicSharedMemorySize, s1_smem);
    const int s3_smem = 2 * 64 * S3P * sizeof(float);  // 67584 B
    cudaFuncSetAttribute(stage3_kernel,
                         cudaFuncAttributeMaxDynamicSharedMemorySize, s3_smem);

    stage1a_kernel<<<dim3(4, 64), 256, s1_smem>>>(x, conv_w, in_w, dt_w);
    stage1b_kernel<<<256, 256>>>(in_b, dt_b, tr_w);
    scan_kernel<<<8, 32>>>();
    stage3_kernel<<<dim3(8, 128), 256, s3_smem>>>(out_w, out_b, out);
}

// round 8
// speedup vs baseline: 2.4791x; 1.0990x over previous
#include <cuda_runtime.h>
#include <cstddef>
#include <cstdint>

#define BB 4
#define TT 4096
#define DD 1024
#define NN 64
#define RR 16
#define KK 4
#define BT (BB * TT)
#define SG 32    // scan prefetch group size

// Scratch (device globals — no allocation allowed)
__device__ float g_mid[4 * 80 * BT];          // split-K partials, [kc][col][row]
__device__ float2 g_dp[BT * NN + SG * NN];    // interleaved {delta, proj}; padded tail
__device__ float g_states[BT * NN];

// ---------------------------------------------------------------------------
// Stage 1a: split-K GEMM partials, 256-row x 80-col tiles, 8x10 fragments.
// grid (4, 64). Dynamic smem.
// ---------------------------------------------------------------------------
#define XP 264   // xs/as pitch

__global__ __launch_bounds__(256, 2) void stage1a_kernel(
    const float* __restrict__ x,
    const float* __restrict__ conv_w,
    const float* __restrict__ in_w,
    const float* __restrict__ dt_w)
{
    extern __shared__ float s1[];
    float* xs = s1;                  // 32 * 264
    float* as = s1 + 32 * XP;        // 32 * 264
    float* wb = s1 + 64 * XP;        // 32 * 80, [kk][c]
    float* scw = wb + 32 * 80;       // 32 * 4

    const int tid = threadIdx.x;
    const int koff = blockIdx.x * 256;
    const int base = blockIdx.y * 256;       // global row (b*T + t)
    const int t0 = base & (TT - 1);          // t within batch (tiles never straddle)
    const int cg = tid & 7;                  // col group (0..7)
    const int rg = tid >> 3;                 // row group (0..31), rows 8*rg..8*rg+7

    float acc[8][10];
#pragma unroll
    for (int i = 0; i < 8; i++)
#pragma unroll
        for (int m = 0; m < 10; m++) acc[i][m] = 0.f;

    for (int k0 = koff; k0 < koff + 256; k0 += 32) {
        // ---- load x tile (259 rows x 32 k), transposed into xs[k][row] ----
        for (int idx = tid; idx < 259 * 8; idx += 256) {
            int ri = idx >> 3, kq = idx & 7;
            int t = (ri < 256) ? (t0 + ri) : (t0 + ri - 259);  // 256..258 -> t0-3..t0-1
            float4 v = make_float4(0.f, 0.f, 0.f, 0.f);
            if (t >= 0) {
                v = *(const float4*)(x + (size_t)(base - t0 + t) * DD + k0 + 4 * kq);
            }
            int kk = 4 * kq;
            xs[(kk + 0) * XP + ri] = v.x;
            xs[(kk + 1) * XP + ri] = v.y;
            xs[(kk + 2) * XP + ri] = v.z;
            xs[(kk + 3) * XP + ri] = v.w;
        }
        // ---- load weights: wb[kk][c] ----
        for (int idx = tid; idx < 80 * 32; idx += 256) {
            int c = idx >> 5, kk = idx & 31;
            float w = (c < 64) ? in_w[(size_t)c * DD + k0 + kk]
                               : dt_w[(size_t)(c - 64) * DD + k0 + kk];
            wb[kk * 80 + c] = w;
        }
        // ---- load conv_w chunk ----
        if (tid < 128) {
            int kk = tid >> 2, j = tid & 3;
            scw[kk * 4 + j] = conv_w[(size_t)(k0 + kk) * KK + j];
        }
        __syncthreads();

        // ---- build conv A-tile: as[kk][r] = x[r] + sum_j cw[j]*x[r-3+j] ----
        for (int idx = tid; idx < 32 * 256; idx += 256) {
            int kk = idx >> 8, r = idx & 255;
            const float* xr = xs + kk * XP;
            float c0 = scw[kk * 4 + 0], c1 = scw[kk * 4 + 1];
            float c2 = scw[kk * 4 + 2], c3 = scw[kk * 4 + 3];
            int rm1 = r - 1; if (rm1 < 0) rm1 += 259;
            int rm2 = r - 2; if (rm2 < 0) rm2 += 259;
            int rm3 = r - 3; if (rm3 < 0) rm3 += 259;
            float v = xr[r];
            v = fmaf(c3, xr[r], v);
            v = fmaf(c2, xr[rm1], v);
            v = fmaf(c1, xr[rm2], v);
            v = fmaf(c0, xr[rm3], v);
            as[kk * XP + r] = v;
        }
        __syncthreads();

        // ---- FFMA main loop: 8 rows x (8 conv-cols + 2 dt-cols) ----
#pragma unroll 4
        for (int kk = 0; kk < 32; kk++) {
            float4 av0 = *(float4*)(as + kk * XP + 8 * rg);
            float4 av1 = *(float4*)(as + kk * XP + 8 * rg + 4);
            float4 xv0 = *(float4*)(xs + kk * XP + 8 * rg);
            float4 xv1 = *(float4*)(xs + kk * XP + 8 * rg + 4);
            float a[8] = {av0.x, av0.y, av0.z, av0.w, av1.x, av1.y, av1.z, av1.w};
            float xw[8] = {xv0.x, xv0.y, xv0.z, xv0.w, xv1.x, xv1.y, xv1.z, xv1.w};
            const float* wk = wb + kk * 80;
            float b[8];
#pragma unroll
            for (int m = 0; m < 8; m++) b[m] = wk[cg + 8 * m];
            float bd0 = wk[64 + cg];
            float bd1 = wk[72 + cg];
#pragma unroll
            for (int i = 0; i < 8; i++) {
#pragma unroll
                for (int m = 0; m < 8; m++)
                    acc[i][m] = fmaf(a[i], b[m], acc[i][m]);
                acc[i][8] = fmaf(xw[i], bd0, acc[i][8]);
                acc[i][9] = fmaf(xw[i], bd1, acc[i][9]);
            }
        }
        __syncthreads();
    }

    // ---- write partials, column-major g_mid[kc][c][row], float4 stores ----
    {
        float* mid = g_mid + (size_t)blockIdx.x * 80 * BT;
        size_t row0 = base + 8 * rg;
#pragma unroll
        for (int m = 0; m < 10; m++) {
            int c = (m < 8) ? (cg + 8 * m) : (64 + 8 * (m - 8) + cg);
            float* dst = mid + (size_t)c * BT + row0;
            *(float4*)(dst)     = make_float4(acc[0][m], acc[1][m], acc[2][m], acc[3][m]);
            *(float4*)(dst + 4) = make_float4(acc[4][m], acc[5][m], acc[6][m], acc[7][m]);
        }
    }
}

// ---------------------------------------------------------------------------
// Stage 1b: reduce partials, biases, tanh, tr_w GEMM; write interleaved g_dp.
// ---------------------------------------------------------------------------
__global__ __launch_bounds__(256) void stage1b_kernel(
    const float* __restrict__ in_b,
    const float* __restrict__ dt_b,
    const float* __restrict__ tr_w)
{
    __shared__ float sdm[64 * 16];
    __shared__ float str[16 * 64];
    __shared__ float sproj[64 * 68];   // [r][c], pitch 68

    const int tid = threadIdx.x;
    const int base = blockIdx.x * 64;
    const int cg = tid & 15;
    const int rg = tid >> 4;

    for (int idx = tid; idx < NN * RR; idx += 256) {
        int n = idx >> 4, r = idx & 15;
        str[r * 64 + n] = tr_w[idx];
    }

    float dtb = dt_b[cg];
#pragma unroll
    for (int i = 0; i < 4; i++) {
        size_t row = base + 4 * rg + i;
#pragma unroll
        for (int m = 0; m < 4; m++) {
            int c = cg + 16 * m;
            float v = in_b[c];
#pragma unroll
            for (int kc = 0; kc < 4; kc++)
                v += g_mid[((size_t)kc * 80 + c) * BT + row];
            sproj[(4 * rg + i) * 68 + c] = v;
        }
        float dm = dtb;
#pragma unroll
        for (int kc = 0; kc < 4; kc++)
            dm += g_mid[((size_t)kc * 80 + 64 + cg) * BT + row];
        sdm[(4 * rg + i) * 16 + cg] = tanhf(dm);
    }
    __syncthreads();

    float a2[4][4];
#pragma unroll
    for (int i = 0; i < 4; i++)
#pragma unroll
        for (int j = 0; j < 4; j++) a2[i][j] = 0.f;
#pragma unroll
    for (int r = 0; r < 16; r++) {
        float d0 = sdm[(4 * rg + 0) * 16 + r];
        float d1 = sdm[(4 * rg + 1) * 16 + r];
        float d2 = sdm[(4 * rg + 2) * 16 + r];
        float d3 = sdm[(4 * rg + 3) * 16 + r];
        float w0 = str[r * 64 + 4 * cg + 0];
        float w1 = str[r * 64 + 4 * cg + 1];
        float w2 = str[r * 64 + 4 * cg + 2];
        float w3 = str[r * 64 + 4 * cg + 3];
        a2[0][0] = fmaf(d0, w0, a2[0][0]); a2[0][1] = fmaf(d0, w1, a2[0][1]);
        a2[0][2] = fmaf(d0, w2, a2[0][2]); a2[0][3] = fmaf(d0, w3, a2[0][3]);
        a2[1][0] = fmaf(d1, w0, a2[1][0]); a2[1][1] = fmaf(d1, w1, a2[1][1]);
        a2[1][2] = fmaf(d1, w2, a2[1][2]); a2[1][3] = fmaf(d1, w3, a2[1][3]);
        a2[2][0] = fmaf(d2, w0, a2[2][0]); a2[2][1] = fmaf(d2, w1, a2[2][1]);
        a2[2][2] = fmaf(d2, w2, a2[2][2]); a2[2][3] = fmaf(d2, w3, a2[2][3]);
        a2[3][0] = fmaf(d3, w0, a2[3][0]); a2[3][1] = fmaf(d3, w1, a2[3][1]);
        a2[3][2] = fmaf(d3, w2, a2[3][2]); a2[3][3] = fmaf(d3, w3, a2[3][3]);
    }
#pragma unroll
    for (int i = 0; i < 4; i++) {
        size_t row = base + 4 * rg + i;
        const float* pr = sproj + (4 * rg + i) * 68 + 4 * cg;
        float4 v0 = make_float4(a2[i][0], pr[0], a2[i][1], pr[1]);
        float4 v1 = make_float4(a2[i][2], pr[2], a2[i][3], pr[3]);
        float* dst = (float*)(g_dp + row * NN + 4 * cg);
        *(float4*)(dst) = v0;
        *(float4*)(dst + 4) = v1;
    }
}

// ---------------------------------------------------------------------------
// Stage 2: sequential scan, 256 chains, 24-cycle chain via MUFU.TANH.
// ---------------------------------------------------------------------------
__device__ __forceinline__ float fast_tanh(float v) {
    float r;
    asm("tanh.approx.f32 %0, %1;" : "=f"(r) : "f"(v));
    return r;
}

__global__ __launch_bounds__(32) void scan_kernel()
{
    const int chain = blockIdx.x * 32 + threadIdx.x;   // 8 blocks x 32 threads
    const int b = chain >> 6;
    const int n = chain & 63;
    const float2* pdp = g_dp + (size_t)b * TT * NN + n;
    float* ps = g_states + (size_t)b * TT * NN + n;

    float s = 0.f;

    float2 dpA[SG];   // .x = d/2, .y = p
#pragma unroll
    for (int i = 0; i < SG; i++) {
        float2 v = pdp[i * NN];
        dpA[i] = make_float2(0.5f * v.x, v.y);
    }

    for (int t0 = 0; t0 < TT; t0 += SG) {
        float2 dpB[SG];
        int tn = t0 + SG;
#pragma unroll
        for (int i = 0; i < SG; i++) dpB[i] = pdp[(tn + i) * NN];
#pragma unroll
        for (int i = 0; i < SG; i++) {
            float hd = dpA[i].x, p = dpA[i].y;
            float h = fmaf(s, 0.5f, hd);     // chain +4
            float th = fast_tanh(h);         // +16
            float hp = h + p;                // off-chain
            s = fmaf(h, th, hp);             // +4
            ps[(t0 + i) * NN] = s;
        }
#pragma unroll
        for (int i = 0; i < SG; i++) {
            dpA[i] = make_float2(0.5f * dpB[i].x, dpB[i].y);
        }
    }
}

// ---------------------------------------------------------------------------
// Stage 3: out = states @ out_w^T + out_b via split-tf32 mma.sync.
// Block 128(M) x 64(N), 8 warps, warp tile 32x32 (2 m16 x 4 n8 frags), K=64.
// D += a_hi*b_hi + a_hi*b_lo + a_lo*b_hi  (error ~2^-21, fp32-like).
// ---------------------------------------------------------------------------
#define S3PAD 68

__device__ __forceinline__ uint32_t tf32_hi(float x) {
    uint32_t r;
    asm("cvt.rna.tf32.f32 %0, %1;" : "=r"(r) : "f"(x));
    return r;
}

__device__ __forceinline__ void mma_tf32(float4& d,
                                         uint32_t a0, uint32_t a1, uint32_t a2, uint32_t a3,
                                         uint32_t b0, uint32_t b1) {
    asm("mma.sync.aligned.m16n8k8.row.col.f32.tf32.tf32.f32 "
        "{%0,%1,%2,%3}, {%4,%5,%6,%7}, {%8,%9}, {%0,%1,%2,%3};"
        : "+f"(d.x), "+f"(d.y), "+f"(d.z), "+f"(d.w)
        : "r"(a0), "r"(a1), "r"(a2), "r"(a3), "r"(b0), "r"(b1));
}

__global__ __launch_bounds__(256) void stage3_kernel(
    const float* __restrict__ out_w,
    const float* __restrict__ out_b,
    float* __restrict__ out)
{
    extern __shared__ float smem3[];
    float* sA = smem3;                 // [128][S3PAD]  states rows (k contiguous)
    float* sB = smem3 + 128 * S3PAD;   // [64][S3PAD]   out_w rows  (k contiguous)

    const int tid = threadIdx.x;
    const int rbase = blockIdx.y * 128;
    const int cbase = blockIdx.x * 64;
    const int warp = tid >> 5;
    const int lane = tid & 31;
    const int wm = warp >> 1;          // 0..3 -> M offset 32*wm
    const int wn = warp & 1;           // 0..1 -> N offset 32*wn
    const int g = lane >> 2;           // group id (0..7)
    const int tg = lane & 3;           // thread in group (0..3)

    // load A tile: direct row-major copy (coalesced float4)
    for (int idx = tid; idx < 128 * 16; idx += 256) {
        int r = idx >> 4, q = idx & 15;
        float4 v = *(const float4*)(g_states + (size_t)(rbase + r) * NN + 4 * q);
        *(float4*)(sA + r * S3PAD + 4 * q) = v;
    }
    // load B tile: out_w rows
    for (int idx = tid; idx < 64 * 16; idx += 256) {
        int c = idx >> 4, q = idx & 15;
        float4 v = *(const float4*)(out_w + (size_t)(cbase + c) * NN + 4 * q);
        *(float4*)(sB + c * S3PAD + 4 * q) = v;
    }
    __syncthreads();

    float4 acc[2][4];
#pragma unroll
    for (int i = 0; i < 2; i++)
#pragma unroll
        for (int j = 0; j < 4; j++) acc[i][j] = make_float4(0.f, 0.f, 0.f, 0.f);

#pragma unroll
    for (int k0 = 0; k0 < 64; k0 += 8) {
        // ---- A fragments (2 m16 tiles), hi/lo split ----
        uint32_t ahi[2][4], alo[2][4];
#pragma unroll
        for (int mf = 0; mf < 2; mf++) {
            int r0 = wm * 32 + mf * 16 + g;
            float av[4];
            av[0] = sA[r0 * S3PAD + k0 + tg];
            av[1] = sA[(r0 + 8) * S3PAD + k0 + tg];
            av[2] = sA[r0 * S3PAD + k0 + tg + 4];
            av[3] = sA[(r0 + 8) * S3PAD + k0 + tg + 4];
#pragma unroll
            for (int q = 0; q < 4; q++) {
                uint32_t h = tf32_hi(av[q]);
                ahi[mf][q] = h;
                alo[mf][q] = tf32_hi(av[q] - __uint_as_float(h));
            }
        }
        // ---- B fragments (4 n8 tiles), hi/lo split ----
        uint32_t bhi[4][2], blo[4][2];
#pragma unroll
        for (int nf = 0; nf < 4; nf++) {
            int c0 = wn * 32 + nf * 8 + g;
            float bv[2];
            bv[0] = sB[c0 * S3PAD + k0 + tg];
            bv[1] = sB[c0 * S3PAD + k0 + tg + 4];
#pragma unroll
            for (int q = 0; q < 2; q++) {
                uint32_t h = tf32_hi(bv[q]);
                bhi[nf][q] = h;
                blo[nf][q] = tf32_hi(bv[q] - __uint_as_float(h));
            }
        }
        // ---- 3-pass split-tf32 MMA ----
#pragma unroll
        for (int mf = 0; mf < 2; mf++) {
#pragma unroll
            for (int nf = 0; nf < 4; nf++) {
                mma_tf32(acc[mf][nf], alo[mf][0], alo[mf][1], alo[mf][2], alo[mf][3],
                         bhi[nf][0], bhi[nf][1]);
                mma_tf32(acc[mf][nf], ahi[mf][0], ahi[mf][1], ahi[mf][2], ahi[mf][3],
                         blo[nf][0], blo[nf][1]);
                mma_tf32(acc[mf][nf], ahi[mf][0], ahi[mf][1], ahi[mf][2], ahi[mf][3],
                         bhi[nf][0], bhi[nf][1]);
            }
        }
    }

    // ---- epilogue: bias + store (float2 per c0/c1 pair) ----
#pragma unroll
    for (int nf = 0; nf < 4; nf++) {
        int c = cbase + wn * 32 + nf * 8 + 2 * tg;
        float b0 = out_b[c], b1 = out_b[c + 1];
#pragma unroll
        for (int mf = 0; mf < 2; mf++) {
            int r0 = rbase + wm * 32 + mf * 16 + g;
            float4 v = acc[mf][nf];
            *(float2*)(out + (size_t)r0 * DD + c) = make_float2(v.x + b0, v.y + b1);
            *(float2*)(out + (size_t)(r0 + 8) * DD + c) = make_float2(v.z + b0, v.w + b1);
        }
    }
}

// ---------------------------------------------------------------------------
extern "C" void kernel_launch(void* const* d_in, const int* in_sizes, int n_in,
                              void* d_out, int out_size)
{
    const float* x      = (const float*)d_in[0];
    const float* conv_w = (const float*)d_in[1];
    const float* in_w   = (const float*)d_in[2];
    const float* in_b   = (const float*)d_in[3];
    const float* dt_w   = (const float*)d_in[4];
    const float* dt_b   = (const float*)d_in[5];
    const float* tr_w   = (const float*)d_in[6];
    const float* out_w  = (const float*)d_in[7];
    const float* out_b  = (const float*)d_in[8];
    float* out = (float*)d_out;

    const int s1_smem = (64 * XP + 32 * 80 + 32 * 4) * sizeof(float);  // 78336 B
    cudaFuncSetAttribute(stage1a_kernel,
                         cudaFuncAttributeMaxDynamicSharedMemorySize, s1_smem);
    const int s3_smem = (128 + 64) * S3PAD * sizeof(float);  // 52224 B
    cudaFuncSetAttribute(stage3_kernel,
                         cudaFuncAttributeMaxDynamicSharedMemorySize, s3_smem);

    stage1a_kernel<<<dim3(4, 64), 256, s1_smem>>>(x, conv_w, in_w, dt_w);
    stage1b_kernel<<<256, 256>>>(in_b, dt_b, tr_w);
    scan_kernel<<<8, 32>>>();
    stage3_kernel<<<dim3(16, 128), 256, s3_smem>>>(out_w, out_b, out);
}